// round 3
// baseline (speedup 1.0000x reference)
#include <cuda_runtime.h>
#include <cstdint>

typedef unsigned long long u64;

// out layout (fp32): [0,BS) imputed | [BS,2BS) disc | [2BS,3BS) latent | [3BS,4BS) recon
// BS = B*16

__device__ float g_dec_recon[16];  // batch-independent decoder output (recomputed per launch)

// ---- activations ----------------------------------------------------------
__device__ __forceinline__ float fast_ex2(float x) {
    float y; asm("ex2.approx.f32 %0, %1;" : "=f"(y) : "f"(x)); return y;
}
__device__ __forceinline__ float fast_rcp(float x) {
    float y; asm("rcp.approx.f32 %0, %1;" : "=f"(y) : "f"(x)); return y;
}
// accurate (~1e-7): generator recurrence + decoder
__device__ __forceinline__ float sigmoidf_(float x) {
    return fast_rcp(1.0f + fast_ex2(-1.4426950408889634f * x));
}
__device__ __forceinline__ float tanhf_(float x) {
    float t = fast_ex2(-2.8853900817779268f * x);
    return fmaf(2.0f, fast_rcp(1.0f + t), -1.0f);
}
// fast (~5e-4 worst case): discriminator (feedforward) only
__device__ __forceinline__ float tanh_a(float x) {
    float y; asm("tanh.approx.f32 %0, %1;" : "=f"(y) : "f"(x)); return y;
}
__device__ __forceinline__ float sig_a(float x) {
    return fmaf(0.5f, tanh_a(0.5f * x), 0.5f);
}

// ---- packed f32x2 helpers -------------------------------------------------
__device__ __forceinline__ u64 pk(float x) {
    u64 r; unsigned xu = __float_as_uint(x);
    asm("mov.b64 %0, {%1, %1};" : "=l"(r) : "r"(xu));
    return r;
}
__device__ __forceinline__ u64 pk2f(float lo, float hi) {
    u64 r; unsigned a = __float_as_uint(lo), b = __float_as_uint(hi);
    asm("mov.b64 %0, {%1, %2};" : "=l"(r) : "r"(a), "r"(b));
    return r;
}
__device__ __forceinline__ void upk(u64 v, float& lo, float& hi) {
    unsigned a, b;
    asm("mov.b64 {%0, %1}, %2;" : "=r"(a), "=r"(b) : "l"(v));
    lo = __uint_as_float(a); hi = __uint_as_float(b);
}
__device__ __forceinline__ u64 f2fma(u64 a, u64 b, u64 c) {
    u64 d;
    asm("fma.rn.f32x2 %0, %1, %2, %3;" : "=l"(d) : "l"(a), "l"(b), "l"(c));
    return d;
}

// ---------------------------------------------------------------------------
// packed LSTM step, H=16, scalar input cc, ONE direction per thread.
// Up[((g*8+p)*16+k)] = (W[g*16+2p][k], W[g*16+2p+1][k]); g: 0=i,1=f,2=g,3=o
// ---------------------------------------------------------------------------
__device__ __forceinline__ void lstm_step_packed(
    float h[16], float c[16], float cc,
    const u64* __restrict__ Up, const u64* __restrict__ Wp, const u64* __restrict__ Bp)
{
    u64 hh[16];
#pragma unroll
    for (int k = 0; k < 16; k++) hh[k] = pk(h[k]);
    u64 ccp = pk(cc);
    float hn[16];
#pragma unroll
    for (int p = 0; p < 8; p++) {
        u64 ai = f2fma(ccp, Wp[p],      Bp[p]);
        u64 af = f2fma(ccp, Wp[8 + p],  Bp[8 + p]);
        u64 ag = f2fma(ccp, Wp[16 + p], Bp[16 + p]);
        u64 ao = f2fma(ccp, Wp[24 + p], Bp[24 + p]);
#pragma unroll
        for (int k = 0; k < 16; k += 2) {
            ulonglong2 wi = *(const ulonglong2*)(Up + (p) * 16 + k);
            ulonglong2 wf = *(const ulonglong2*)(Up + (8 + p) * 16 + k);
            ulonglong2 wg = *(const ulonglong2*)(Up + (16 + p) * 16 + k);
            ulonglong2 wo = *(const ulonglong2*)(Up + (24 + p) * 16 + k);
            ai = f2fma(hh[k], wi.x, ai); ai = f2fma(hh[k + 1], wi.y, ai);
            af = f2fma(hh[k], wf.x, af); af = f2fma(hh[k + 1], wf.y, af);
            ag = f2fma(hh[k], wg.x, ag); ag = f2fma(hh[k + 1], wg.y, ag);
            ao = f2fma(hh[k], wo.x, ao); ao = f2fma(hh[k + 1], wo.y, ao);
        }
        float i0, i1, f0, f1, g0, g1, o0, o1;
        upk(ai, i0, i1); upk(af, f0, f1); upk(ag, g0, g1); upk(ao, o0, o1);
        float cn0 = fmaf(sigmoidf_(f0), c[2 * p],     sigmoidf_(i0) * tanhf_(g0));
        float cn1 = fmaf(sigmoidf_(f1), c[2 * p + 1], sigmoidf_(i1) * tanhf_(g1));
        c[2 * p] = cn0; c[2 * p + 1] = cn1;
        hn[2 * p]     = sigmoidf_(o0) * tanhf_(cn0);
        hn[2 * p + 1] = sigmoidf_(o1) * tanhf_(cn1);
    }
#pragma unroll
    for (int k = 0; k < 16; k++) h[k] = hn[k];
}

// ---------------------------------------------------------------------------
// Generator kernel: 256 threads = 128 rows/block, 2 threads (fwd/bwd) per row.
// Last block computes the batch-independent decoder recurrence concurrently.
// ---------------------------------------------------------------------------
__global__ void __launch_bounds__(256)
gen_kernel(const float* __restrict__ values, const int* __restrict__ masks,
           const float* __restrict__ gfU, const float* __restrict__ gfW, const float* __restrict__ gfb,
           const float* __restrict__ gbU, const float* __restrict__ gbW, const float* __restrict__ gbb,
           const float* __restrict__ impW, const float* __restrict__ impB,
           const float* __restrict__ fcW, const float* __restrict__ fcB,
           const float* __restrict__ dWih, const float* __restrict__ dWhh,
           const float* __restrict__ db_, const float* __restrict__ dOW, const float* __restrict__ dOB,
           float* __restrict__ out, int B)
{
    __shared__ __align__(16) u64 sUfp[512], sUbp[512];
    __shared__ __align__(16) u64 sWfp[32], sWbp[32], sBfp[32], sBbp[32];
    __shared__ __align__(16) u64 sFcp[128], sFcBp[8];
    __shared__ __align__(16) float sStage[1024];
    __shared__ float sImpW[16];
    __shared__ float sXV[16 * 128], sMV[16 * 128];
    __shared__ float sImpB;

    const int NT = 256;
    int tid = threadIdx.x;

    // ---- decoder block: batch-independent recon, 16 serial steps ----
    if (blockIdx.x == gridDim.x - 1) {
        float* rWih = sStage;            // 1024
        float* rWhh = (float*)sUfp;      // 1024
        float* rm   = (float*)sUbp;      // scratch
        float* rb  = rm;       float* rOW = rm + 64;
        float* rsh = rm + 80;  float* rsc = rm + 96;  float* rgat = rm + 112;

        for (int i = tid; i < 1024; i += NT) { rWih[i] = dWih[i]; rWhh[i] = dWhh[i]; }
        if (tid < 64) rb[tid] = db_[tid];
        if (tid < 16) rOW[tid] = dOW[tid];
        __syncthreads();
        if (tid < 16) {
            float si = rb[tid], sg = rb[tid + 32], so = rb[tid + 48];
#pragma unroll
            for (int k = 0; k < 16; k++) {
                si = fmaf(128.f, rWih[tid * 16 + k], si);
                sg = fmaf(128.f, rWih[(tid + 32) * 16 + k], sg);
                so = fmaf(128.f, rWih[(tid + 48) * 16 + k], so);
            }
            float c = sigmoidf_(si) * tanhf_(sg);
            rsc[tid] = c; rsh[tid] = sigmoidf_(so) * tanhf_(c);
        }
        __syncthreads();
        for (int s = 0; s < 16; s++) {
            if (tid < 64) {
                float acc = rb[tid];
#pragma unroll
                for (int k = 0; k < 16; k++)
                    acc = fmaf(rsc[k], rWih[tid * 16 + k], fmaf(rsh[k], rWhh[tid * 16 + k], acc));
                rgat[tid] = acc;
            }
            __syncthreads();
            if (tid < 16) {
                float c = fmaf(sigmoidf_(rgat[tid + 16]), rsc[tid],
                               sigmoidf_(rgat[tid]) * tanhf_(rgat[tid + 32]));
                rsc[tid] = c; rsh[tid] = sigmoidf_(rgat[tid + 48]) * tanhf_(c);
            }
            __syncthreads();
            if (tid == 0) {
                float r = dOB[0];
#pragma unroll
                for (int k = 0; k < 16; k++) r = fmaf(rsh[k], rOW[k], r);
                g_dec_recon[s] = r;
            }
            __syncthreads();
        }
        return;
    }

    // ---- pack weights (coalesced stage -> packed smem) ----
    for (int i = tid; i < 1024; i += NT) sStage[i] = gfU[i];
    __syncthreads();
    for (int i = tid; i < 512; i += NT) {
        int g = i >> 7, p = (i >> 4) & 7, k = i & 15;
        int r0 = g * 16 + 2 * p;
        sUfp[i] = pk2f(sStage[r0 * 16 + k], sStage[r0 * 16 + 16 + k]);
    }
    __syncthreads();
    for (int i = tid; i < 1024; i += NT) sStage[i] = gbU[i];
    __syncthreads();
    for (int i = tid; i < 512; i += NT) {
        int g = i >> 7, p = (i >> 4) & 7, k = i & 15;
        int r0 = g * 16 + 2 * p;
        sUbp[i] = pk2f(sStage[r0 * 16 + k], sStage[r0 * 16 + 16 + k]);
    }
    for (int i = tid; i < 32; i += NT) {
        int g = i >> 3, p = i & 7; int r0 = g * 16 + 2 * p;
        sWfp[i] = pk2f(gfW[r0], gfW[r0 + 1]);  sBfp[i] = pk2f(gfb[r0], gfb[r0 + 1]);
        sWbp[i] = pk2f(gbW[r0], gbW[r0 + 1]);  sBbp[i] = pk2f(gbb[r0], gbb[r0 + 1]);
    }
    for (int i = tid; i < 128; i += NT) {
        int p = i >> 4, k = i & 15; int r0 = 2 * p;
        sFcp[i] = pk2f(fcW[r0 * 16 + k], fcW[r0 * 16 + 16 + k]);
    }
    if (tid < 8)  sFcBp[tid] = pk2f(fcB[2 * tid], fcB[2 * tid + 1]);
    if (tid < 16) sImpW[tid] = impW[tid];
    if (tid == 0) sImpB = impB[0];

    int pair = tid >> 1;       // 0..127  (batch row within block)
    int dir  = tid & 1;        // 0 = fwd, 1 = bwd
    int b    = blockIdx.x * 128 + pair;

    // stage values (even lane) / masks (odd lane) to time-major smem
    if (b < B) {
        if (dir == 0) {
            const float4* v4p = (const float4*)(values + (size_t)b * 16);
#pragma unroll
            for (int i = 0; i < 4; i++) {
                float4 v = __ldg(v4p + i);
                sXV[(4 * i + 0) * 128 + pair] = v.x;
                sXV[(4 * i + 1) * 128 + pair] = v.y;
                sXV[(4 * i + 2) * 128 + pair] = v.z;
                sXV[(4 * i + 3) * 128 + pair] = v.w;
            }
        } else {
            const int4* m4p = (const int4*)(masks + (size_t)b * 16);
#pragma unroll
            for (int i = 0; i < 4; i++) {
                int4 m = __ldg(m4p + i);
                sMV[(4 * i + 0) * 128 + pair] = (float)m.x;
                sMV[(4 * i + 1) * 128 + pair] = (float)m.y;
                sMV[(4 * i + 2) * 128 + pair] = (float)m.z;
                sMV[(4 * i + 3) * 128 + pair] = (float)m.w;
            }
        }
    }
    __syncthreads();
    if (b >= B) return;

    const u64* Up = dir ? sUbp : sUfp;
    const u64* Wp = dir ? sWbp : sWfp;
    const u64* Bp = dir ? sBbp : sBfp;
    float x0v = dir ? -128.0f : 128.0f;

    // ---- init step (x = +-128, h = c = 0) ----
    float h[16], c[16];
    {
        u64 xp = pk(x0v);
#pragma unroll
        for (int p = 0; p < 8; p++) {
            float i0, i1, g0, g1, o0, o1;
            upk(f2fma(xp, Wp[p],      Bp[p]),      i0, i1);
            upk(f2fma(xp, Wp[16 + p], Bp[16 + p]), g0, g1);
            upk(f2fma(xp, Wp[24 + p], Bp[24 + p]), o0, o1);
            float c0 = sigmoidf_(i0) * tanhf_(g0), c1 = sigmoidf_(i1) * tanhf_(g1);
            c[2 * p] = c0; c[2 * p + 1] = c1;
            h[2 * p] = sigmoidf_(o0) * tanhf_(c0);
            h[2 * p + 1] = sigmoidf_(o1) * tanhf_(c1);
        }
    }

    float impb = sImpB;
#pragma unroll 1
    for (int t = 0; t < 16; t++) {
        float xt = sXV[t * 128 + pair];
        float mt = sMV[t * 128 + pair];
        float d = impb;
#pragma unroll
        for (int k = 0; k < 16; k++) d = fmaf(h[k], sImpW[k], d);
        float cc = fmaf(mt, d - xt, xt);     // m in {0,1}
        lstm_step_packed(h, c, cc, Up, Wp, Bp);
    }

    // combine fwd+bwd final h across the thread pair
    float hs[16];
#pragma unroll
    for (int k = 0; k < 16; k++)
        hs[k] = h[k] + __shfl_xor_sync(0xffffffffu, h[k], 1);

    size_t BS = (size_t)B * 16;

    if (dir == 0) {
        // imputed: hs[s]*(1-m) + x*m
        float impv[16];
#pragma unroll
        for (int s = 0; s < 16; s++) {
            float xt = sXV[s * 128 + pair];
            float mt = sMV[s * 128 + pair];
            impv[s] = fmaf(mt, xt - hs[s], hs[s]);
        }
        float4* o4 = reinterpret_cast<float4*>(out + (size_t)b * 16);
#pragma unroll
        for (int i = 0; i < 4; i++)
            o4[i] = make_float4(impv[4 * i], impv[4 * i + 1], impv[4 * i + 2], impv[4 * i + 3]);
    } else {
        // latent = hs @ fcW.T + fcB (packed)
        float lat[16];
#pragma unroll
        for (int p = 0; p < 8; p++) {
            u64 acc = sFcBp[p];
#pragma unroll
            for (int k = 0; k < 16; k += 2) {
                ulonglong2 w = *(const ulonglong2*)(sFcp + p * 16 + k);
                acc = f2fma(pk(hs[k]), w.x, acc);
                acc = f2fma(pk(hs[k + 1]), w.y, acc);
            }
            upk(acc, lat[2 * p], lat[2 * p + 1]);
        }
        float4* l4 = reinterpret_cast<float4*>(out + 2 * BS + (size_t)b * 16);
#pragma unroll
        for (int i = 0; i < 4; i++)
            l4[i] = make_float4(lat[4 * i], lat[4 * i + 1], lat[4 * i + 2], lat[4 * i + 3]);
    }
}

// ---------------------------------------------------------------------------
// Discriminator evaluation (per sample). 'f' gate is dead in the reference.
// ---------------------------------------------------------------------------
__device__ __forceinline__ float disc_eval(float a,
    const u64* __restrict__ sW0p, const u64* __restrict__ sB0p,
    const u64* __restrict__ sW1p, const u64* __restrict__ sB1p,
    const u64* __restrict__ sW2p, const u64* __restrict__ sB2p,
    const u64* __restrict__ sW3p, const u64* __restrict__ sB3p,
    const u64* __restrict__ sW4p, const u64* __restrict__ sB4p,
    const u64* __restrict__ sDowp, float dob0)
{
    u64 aa = pk(a);
    float v0[32];
#pragma unroll
    for (int p = 0; p < 16; p++) {
        float i0, i1, g0, g1, o0, o1;
        upk(f2fma(aa, sW0p[p],      sB0p[p]),      i0, i1);
        upk(f2fma(aa, sW0p[16 + p], sB0p[16 + p]), g0, g1);
        upk(f2fma(aa, sW0p[32 + p], sB0p[32 + p]), o0, o1);
        float c0 = sig_a(i0) * tanh_a(g0), c1 = sig_a(i1) * tanh_a(g1);
        v0[2 * p]     = sig_a(o0) * tanh_a(c0);
        v0[2 * p + 1] = sig_a(o1) * tanh_a(c1);
    }
    float v1[16];
#pragma unroll
    for (int p = 0; p < 8; p++) {
        u64 ai = sB1p[p], ag = sB1p[8 + p], ao = sB1p[16 + p];
#pragma unroll
        for (int k = 0; k < 32; k += 2) {
            ulonglong2 wi = *(const ulonglong2*)(sW1p + (p) * 32 + k);
            ulonglong2 wg = *(const ulonglong2*)(sW1p + (8 + p) * 32 + k);
            ulonglong2 wo = *(const ulonglong2*)(sW1p + (16 + p) * 32 + k);
            u64 x0 = pk(v0[k]), x1 = pk(v0[k + 1]);
            ai = f2fma(x0, wi.x, ai); ai = f2fma(x1, wi.y, ai);
            ag = f2fma(x0, wg.x, ag); ag = f2fma(x1, wg.y, ag);
            ao = f2fma(x0, wo.x, ao); ao = f2fma(x1, wo.y, ao);
        }
        float i0, i1, g0, g1, o0, o1;
        upk(ai, i0, i1); upk(ag, g0, g1); upk(ao, o0, o1);
        float c0 = sig_a(i0) * tanh_a(g0), c1 = sig_a(i1) * tanh_a(g1);
        v1[2 * p]     = sig_a(o0) * tanh_a(c0);
        v1[2 * p + 1] = sig_a(o1) * tanh_a(c1);
    }
    float v2[8];
#pragma unroll
    for (int p = 0; p < 4; p++) {
        u64 ai = sB2p[p], ag = sB2p[4 + p], ao = sB2p[8 + p];
#pragma unroll
        for (int k = 0; k < 16; k += 2) {
            ulonglong2 wi = *(const ulonglong2*)(sW2p + (p) * 16 + k);
            ulonglong2 wg = *(const ulonglong2*)(sW2p + (4 + p) * 16 + k);
            ulonglong2 wo = *(const ulonglong2*)(sW2p + (8 + p) * 16 + k);
            u64 x0 = pk(v1[k]), x1 = pk(v1[k + 1]);
            ai = f2fma(x0, wi.x, ai); ai = f2fma(x1, wi.y, ai);
            ag = f2fma(x0, wg.x, ag); ag = f2fma(x1, wg.y, ag);
            ao = f2fma(x0, wo.x, ao); ao = f2fma(x1, wo.y, ao);
        }
        float i0, i1, g0, g1, o0, o1;
        upk(ai, i0, i1); upk(ag, g0, g1); upk(ao, o0, o1);
        float c0 = sig_a(i0) * tanh_a(g0), c1 = sig_a(i1) * tanh_a(g1);
        v2[2 * p]     = sig_a(o0) * tanh_a(c0);
        v2[2 * p + 1] = sig_a(o1) * tanh_a(c1);
    }
    float v3[16];
#pragma unroll
    for (int p = 0; p < 8; p++) {
        u64 ai = sB3p[p], ag = sB3p[8 + p], ao = sB3p[16 + p];
#pragma unroll
        for (int k = 0; k < 8; k += 2) {
            ulonglong2 wi = *(const ulonglong2*)(sW3p + (p) * 8 + k);
            ulonglong2 wg = *(const ulonglong2*)(sW3p + (8 + p) * 8 + k);
            ulonglong2 wo = *(const ulonglong2*)(sW3p + (16 + p) * 8 + k);
            u64 x0 = pk(v2[k]), x1 = pk(v2[k + 1]);
            ai = f2fma(x0, wi.x, ai); ai = f2fma(x1, wi.y, ai);
            ag = f2fma(x0, wg.x, ag); ag = f2fma(x1, wg.y, ag);
            ao = f2fma(x0, wo.x, ao); ao = f2fma(x1, wo.y, ao);
        }
        float i0, i1, g0, g1, o0, o1;
        upk(ai, i0, i1); upk(ag, g0, g1); upk(ao, o0, o1);
        float c0 = sig_a(i0) * tanh_a(g0), c1 = sig_a(i1) * tanh_a(g1);
        v3[2 * p]     = sig_a(o0) * tanh_a(c0);
        v3[2 * p + 1] = sig_a(o1) * tanh_a(c1);
    }
    float v4[32];
#pragma unroll
    for (int p = 0; p < 16; p++) {
        u64 ai = sB4p[p], ag = sB4p[16 + p], ao = sB4p[32 + p];
#pragma unroll
        for (int k = 0; k < 16; k += 2) {
            ulonglong2 wi = *(const ulonglong2*)(sW4p + (p) * 16 + k);
            ulonglong2 wg = *(const ulonglong2*)(sW4p + (16 + p) * 16 + k);
            ulonglong2 wo = *(const ulonglong2*)(sW4p + (32 + p) * 16 + k);
            u64 x0 = pk(v3[k]), x1 = pk(v3[k + 1]);
            ai = f2fma(x0, wi.x, ai); ai = f2fma(x1, wi.y, ai);
            ag = f2fma(x0, wg.x, ag); ag = f2fma(x1, wg.y, ag);
            ao = f2fma(x0, wo.x, ao); ao = f2fma(x1, wo.y, ao);
        }
        float i0, i1, g0, g1, o0, o1;
        upk(ai, i0, i1); upk(ag, g0, g1); upk(ao, o0, o1);
        float c0 = sig_a(i0) * tanh_a(g0), c1 = sig_a(i1) * tanh_a(g1);
        v4[2 * p]     = sig_a(o0) * tanh_a(c0);
        v4[2 * p + 1] = sig_a(o1) * tanh_a(c1);
    }
    u64 acc = 0;  // (0.0f, 0.0f)
#pragma unroll
    for (int p = 0; p < 16; p++)
        acc = f2fma(pk2f(v4[2 * p], v4[2 * p + 1]), sDowp[p], acc);
    float lo, hi; upk(acc, lo, hi);
    return lo + hi + dob0;
}

// ---------------------------------------------------------------------------
// Discriminator kernel: 512 blocks x 256 threads, 4 samples/thread.
// Also fills the (batch-independent) reconstructed section.
// ---------------------------------------------------------------------------
__global__ void __launch_bounds__(256)
disc_kernel(const float* __restrict__ W0, const float* __restrict__ b0,
            const float* __restrict__ W1, const float* __restrict__ b1,
            const float* __restrict__ W2, const float* __restrict__ b2,
            const float* __restrict__ W3, const float* __restrict__ b3,
            const float* __restrict__ W4, const float* __restrict__ b4,
            const float* __restrict__ dow, const float* __restrict__ dob,
            float* out, int BS)
{
    __shared__ __align__(16) float stage[2048];
    __shared__ __align__(16) u64 sW1p[768], sW4p[768], sW2p[192], sW3p[192], sW0p[48];
    __shared__ __align__(16) u64 sB0p[48], sB1p[24], sB2p[12], sB3p[24], sB4p[48], sDowp[16];
    __shared__ float sRec[16];
    __shared__ float sDob;

    const int NT = 256;
    int tid = threadIdx.x;

    // --- stage + pack W1 ---
    for (int i = tid; i < 2048; i += NT) stage[i] = W1[i];
    __syncthreads();
    for (int i = tid; i < 768; i += NT) {
        int t = i >> 8, p = (i >> 5) & 7, k = i & 31;
        int r0 = ((t == 0) ? 0 : (t == 1) ? 32 : 48) + 2 * p;
        sW1p[i] = pk2f(stage[r0 * 32 + k], stage[r0 * 32 + 32 + k]);
    }
    __syncthreads();
    // --- stage + pack W4 ---
    for (int i = tid; i < 2048; i += NT) stage[i] = W4[i];
    __syncthreads();
    for (int i = tid; i < 768; i += NT) {
        int t = i >> 8, p = (i >> 4) & 15, k = i & 15;
        int r0 = ((t == 0) ? 0 : (t == 1) ? 64 : 96) + 2 * p;
        sW4p[i] = pk2f(stage[r0 * 16 + k], stage[r0 * 16 + 16 + k]);
    }
    __syncthreads();
    // --- stage + pack W2, W3 ---
    for (int i = tid; i < 512; i += NT) { stage[i] = W2[i]; stage[512 + i] = W3[i]; }
    __syncthreads();
    for (int i = tid; i < 192; i += NT) {
        { int t = i >> 6, p = (i >> 4) & 3, k = i & 15;
          int r0 = ((t == 0) ? 0 : (t == 1) ? 16 : 24) + 2 * p;
          sW2p[i] = pk2f(stage[r0 * 16 + k], stage[r0 * 16 + 16 + k]); }
        { int t = i >> 6, p = (i >> 3) & 7, k = i & 7;
          int r0 = ((t == 0) ? 0 : (t == 1) ? 32 : 48) + 2 * p;
          sW3p[i] = pk2f(stage[512 + r0 * 8 + k], stage[512 + r0 * 8 + 8 + k]); }
    }
    // --- small arrays direct from global ---
    for (int i = tid; i < 48; i += NT) {
        int t = i >> 4, p = i & 15;
        int r0 = ((t == 0) ? 0 : (t == 1) ? 64 : 96) + 2 * p;
        sW0p[i] = pk2f(W0[r0], W0[r0 + 1]);
        sB0p[i] = pk2f(b0[r0], b0[r0 + 1]);
        sB4p[i] = pk2f(b4[r0], b4[r0 + 1]);
    }
    for (int i = tid; i < 24; i += NT) {
        int t = i >> 3, p = i & 7;
        int r0 = ((t == 0) ? 0 : (t == 1) ? 32 : 48) + 2 * p;
        sB1p[i] = pk2f(b1[r0], b1[r0 + 1]);
        sB3p[i] = pk2f(b3[r0], b3[r0 + 1]);
    }
    for (int i = tid; i < 12; i += NT) {
        int t = i >> 2, p = i & 3;
        int r0 = ((t == 0) ? 0 : (t == 1) ? 16 : 24) + 2 * p;
        sB2p[i] = pk2f(b2[r0], b2[r0 + 1]);
    }
    for (int i = tid; i < 16; i += NT) sDowp[i] = pk2f(dow[2 * i], dow[2 * i + 1]);
    if (tid < 16) sRec[tid] = g_dec_recon[tid];
    if (tid == 0) sDob = dob[0];
    __syncthreads();

    int stride = gridDim.x * NT;
    int base = blockIdx.x * NT + tid;
    float dob0 = sDob;
    float rec = sRec[base & 15];   // stride % 16 == 0 -> constant per thread

    float av[4];
#pragma unroll
    for (int it = 0; it < 4; it++) {
        int idx = base + it * stride;
        av[it] = (idx < BS) ? out[idx] : 0.0f;
    }
#pragma unroll 1
    for (int it = 0; it < 4; it++) {
        int idx = base + it * stride;
        if (idx >= BS) break;
        float r = disc_eval(av[it], sW0p, sB0p, sW1p, sB1p, sW2p, sB2p,
                            sW3p, sB3p, sW4p, sB4p, sDowp, dob0);
        out[(size_t)BS + idx] = r;
        out[3 * (size_t)BS + idx] = rec;
    }
}

// ---------------------------------------------------------------------------
extern "C" void kernel_launch(void* const* d_in, const int* in_sizes, int n_in,
                              void* d_out, int out_size)
{
    const float* values = (const float*)d_in[0];
    const int*   masks  = (const int*)  d_in[1];
    const float* gfW = (const float*)d_in[2];
    const float* gfU = (const float*)d_in[3];
    const float* gfb = (const float*)d_in[4];
    const float* gbW = (const float*)d_in[5];
    const float* gbU = (const float*)d_in[6];
    const float* gbb = (const float*)d_in[7];
    const float* impW = (const float*)d_in[8];
    const float* impB = (const float*)d_in[9];
    const float* fcW  = (const float*)d_in[10];
    const float* fcB  = (const float*)d_in[11];
    const float* dWih = (const float*)d_in[12];
    const float* dWhh = (const float*)d_in[13];
    const float* db_  = (const float*)d_in[14];
    const float* dOW  = (const float*)d_in[15];
    const float* dOB  = (const float*)d_in[16];
    const float* dow  = (const float*)d_in[17];
    const float* dob  = (const float*)d_in[18];
    const float* W0 = (const float*)d_in[19]; const float* b0 = (const float*)d_in[20];
    const float* W1 = (const float*)d_in[21]; const float* b1 = (const float*)d_in[22];
    const float* W2 = (const float*)d_in[23]; const float* b2 = (const float*)d_in[24];
    const float* W3 = (const float*)d_in[25]; const float* b3 = (const float*)d_in[26];
    const float* W4 = (const float*)d_in[27]; const float* b4 = (const float*)d_in[28];

    float* out = (float*)d_out;
    int B  = in_sizes[0] / 16;     // 32768
    int BS = B * 16;               // 524288

    gen_kernel<<<B / 128 + 1, 256>>>(values, masks, gfU, gfW, gfb, gbU, gbW, gbb,
                                     impW, impB, fcW, fcB,
                                     dWih, dWhh, db_, dOW, dOB, out, B);
    disc_kernel<<<512, 256>>>(W0, b0, W1, b1, W2, b2, W3, b3, W4, b4,
                              dow, dob, out, BS);
}

// round 5
// speedup vs baseline: 1.0803x; 1.0803x over previous
#include <cuda_runtime.h>
#include <cstdint>

// out layout (fp32): [0,BS) imputed | [BS,2BS) disc | [2BS,3BS) latent | [3BS,4BS) recon
// BS = B*16

__device__ float g_dec_recon[16];  // batch-independent decoder output

// ---- activations ----------------------------------------------------------
__device__ __forceinline__ float fast_ex2(float x) {
    float y; asm("ex2.approx.f32 %0, %1;" : "=f"(y) : "f"(x)); return y;
}
__device__ __forceinline__ float fast_rcp(float x) {
    float y; asm("rcp.approx.f32 %0, %1;" : "=f"(y) : "f"(x)); return y;
}
// accurate (~1e-7): generator recurrence + decoder
__device__ __forceinline__ float sigmoidf_(float x) {
    return fast_rcp(1.0f + fast_ex2(-1.4426950408889634f * x));
}
__device__ __forceinline__ float tanhf_(float x) {
    float t = fast_ex2(-2.8853900817779268f * x);
    return fmaf(2.0f, fast_rcp(1.0f + t), -1.0f);
}
// fast (feedforward disc only; proven rel_err ~3e-6 in round 3)
__device__ __forceinline__ float tanh_a(float x) {
    float y; asm("tanh.approx.f32 %0, %1;" : "=f"(y) : "f"(x)); return y;
}

// dot over N floats (N multiple of 4, 16B-aligned smem rows)
template <int N>
__device__ __forceinline__ float dotN(const float* __restrict__ w,
                                      const float* __restrict__ v, float acc) {
#pragma unroll
    for (int k = 0; k < N; k += 4) {
        float4 wv = *reinterpret_cast<const float4*>(w + k);
        acc = fmaf(v[k + 0], wv.x, acc);
        acc = fmaf(v[k + 1], wv.y, acc);
        acc = fmaf(v[k + 2], wv.z, acc);
        acc = fmaf(v[k + 3], wv.w, acc);
    }
    return acc;
}

// ===========================================================================
// Generator: 256 threads = 128 rows/block, 2 threads per row (even=fwd, odd=bwd).
// All state scalar float (no 64-bit register arrays -> no spill).
// Last block computes the batch-independent decoder recurrence instead.
// ===========================================================================
__global__ void __launch_bounds__(256)
gen_kernel(const float* __restrict__ values, const int* __restrict__ masks,
           const float* __restrict__ gfU, const float* __restrict__ gfW, const float* __restrict__ gfb,
           const float* __restrict__ gbU, const float* __restrict__ gbW, const float* __restrict__ gbb,
           const float* __restrict__ impW, const float* __restrict__ impB,
           const float* __restrict__ fcW, const float* __restrict__ fcB,
           const float* __restrict__ dWih, const float* __restrict__ dWhh,
           const float* __restrict__ db_, const float* __restrict__ dOW, const float* __restrict__ dOB,
           float* __restrict__ out, int B)
{
    __shared__ __align__(16) float sU[2][1024];   // [dir][64*16] hidden weights
    __shared__ __align__(16) float sW[2][64];     // [dir][64] input weights
    __shared__ __align__(16) float sB[2][64];     // [dir][64] biases
    __shared__ __align__(16) float sImpW[16], sFcW[256], sFcB[16];
    __shared__ __align__(16) float sXV[16 * 128], sMV[16 * 128];
    __shared__ float sImpB;

    const int NT = 256;
    int tid = threadIdx.x;

    // ---- last block: batch-independent decoder recurrence ----
    if (blockIdx.x == gridDim.x - 1) {
        float* rWih = sXV;                // 1024 floats (sXV has 2048)
        float* rWhh = sXV + 1024;         // 1024 floats
        float* rb   = sMV;       float* rOW = sMV + 64;
        float* rsh  = sMV + 80;  float* rsc = sMV + 96;  float* rgat = sMV + 112;

        for (int i = tid; i < 1024; i += NT) { rWih[i] = dWih[i]; rWhh[i] = dWhh[i]; }
        if (tid < 64) rb[tid] = db_[tid];
        if (tid < 16) rOW[tid] = dOW[tid];
        __syncthreads();
        if (tid < 16) {
            float si = rb[tid], sg = rb[tid + 32], so = rb[tid + 48];
#pragma unroll
            for (int k = 0; k < 16; k++) {
                si = fmaf(128.f, rWih[tid * 16 + k], si);
                sg = fmaf(128.f, rWih[(tid + 32) * 16 + k], sg);
                so = fmaf(128.f, rWih[(tid + 48) * 16 + k], so);
            }
            float c = sigmoidf_(si) * tanhf_(sg);
            rsc[tid] = c; rsh[tid] = sigmoidf_(so) * tanhf_(c);
        }
        __syncthreads();
        for (int s = 0; s < 16; s++) {
            if (tid < 64) {
                float acc = rb[tid];
#pragma unroll
                for (int k = 0; k < 16; k++)
                    acc = fmaf(rsc[k], rWih[tid * 16 + k], fmaf(rsh[k], rWhh[tid * 16 + k], acc));
                rgat[tid] = acc;
            }
            __syncthreads();
            if (tid < 16) {
                float c = fmaf(sigmoidf_(rgat[tid + 16]), rsc[tid],
                               sigmoidf_(rgat[tid]) * tanhf_(rgat[tid + 32]));
                rsc[tid] = c; rsh[tid] = sigmoidf_(rgat[tid + 48]) * tanhf_(c);
            }
            __syncthreads();
            if (tid == 0) {
                float r = dOB[0];
#pragma unroll
                for (int k = 0; k < 16; k++) r = fmaf(rsh[k], rOW[k], r);
                g_dec_recon[s] = r;
            }
            __syncthreads();
        }
        return;
    }

    // ---- load weights (scalar, coalesced) ----
    for (int i = tid; i < 1024; i += NT) { sU[0][i] = gfU[i]; sU[1][i] = gbU[i]; }
    for (int i = tid; i < 64; i += NT) {
        sW[0][i] = gfW[i]; sW[1][i] = gbW[i];
        sB[0][i] = gfb[i]; sB[1][i] = gbb[i];
    }
    for (int i = tid; i < 256; i += NT) sFcW[i] = fcW[i];
    if (tid < 16) { sImpW[tid] = impW[tid]; sFcB[tid] = fcB[tid]; }
    if (tid == 0) sImpB = impB[0];

    int pair = tid >> 1;     // row within block (0..127)
    int dir  = tid & 1;      // 0 = fwd, 1 = bwd
    int b    = blockIdx.x * 128 + pair;

    // stage x (even lane) / m (odd lane), time-major
    if (dir == 0) {
        const float4* v4p = (const float4*)(values + (size_t)b * 16);
#pragma unroll
        for (int i = 0; i < 4; i++) {
            float4 v = __ldg(v4p + i);
            sXV[(4 * i + 0) * 128 + pair] = v.x;
            sXV[(4 * i + 1) * 128 + pair] = v.y;
            sXV[(4 * i + 2) * 128 + pair] = v.z;
            sXV[(4 * i + 3) * 128 + pair] = v.w;
        }
    } else {
        const int4* m4p = (const int4*)(masks + (size_t)b * 16);
#pragma unroll
        for (int i = 0; i < 4; i++) {
            int4 m = __ldg(m4p + i);
            sMV[(4 * i + 0) * 128 + pair] = (float)m.x;
            sMV[(4 * i + 1) * 128 + pair] = (float)m.y;
            sMV[(4 * i + 2) * 128 + pair] = (float)m.z;
            sMV[(4 * i + 3) * 128 + pair] = (float)m.w;
        }
    }
    __syncthreads();

    const float* U  = sU[dir];
    const float* W  = sW[dir];
    const float* Bv = sB[dir];
    float x0 = dir ? -128.0f : 128.0f;

    // ---- init step (h = c = 0): gates = x0*W + b; f gate unused (c=0) ----
    float h[16], c[16];
#pragma unroll
    for (int j = 0; j < 16; j++) {
        float gi = fmaf(x0, W[j],      Bv[j]);
        float gg = fmaf(x0, W[32 + j], Bv[32 + j]);
        float go = fmaf(x0, W[48 + j], Bv[48 + j]);
        float cc = sigmoidf_(gi) * tanhf_(gg);
        c[j] = cc;
        h[j] = sigmoidf_(go) * tanhf_(cc);
    }

    float impb = sImpB;
#pragma unroll 1
    for (int t = 0; t < 16; t++) {
        float xt = sXV[t * 128 + pair];
        float mt = sMV[t * 128 + pair];
        float d = impb;
#pragma unroll
        for (int k = 0; k < 16; k++) d = fmaf(h[k], sImpW[k], d);
        float cc = fmaf(mt, d - xt, xt);      // m in {0,1}

        float hn[16];
#pragma unroll
        for (int j = 0; j < 16; j++) {
            float gi = dotN<16>(U + j * 16,        h, fmaf(cc, W[j],      Bv[j]));
            float gf = dotN<16>(U + (16 + j) * 16, h, fmaf(cc, W[16 + j], Bv[16 + j]));
            float gg = dotN<16>(U + (32 + j) * 16, h, fmaf(cc, W[32 + j], Bv[32 + j]));
            float go = dotN<16>(U + (48 + j) * 16, h, fmaf(cc, W[48 + j], Bv[48 + j]));
            float cn = fmaf(sigmoidf_(gf), c[j], sigmoidf_(gi) * tanhf_(gg));
            c[j] = cn;
            hn[j] = sigmoidf_(go) * tanhf_(cn);
        }
#pragma unroll
        for (int j = 0; j < 16; j++) h[j] = hn[j];
    }

    // combine fwd + bwd across the thread pair
    float hs[16];
#pragma unroll
    for (int k = 0; k < 16; k++)
        hs[k] = h[k] + __shfl_xor_sync(0xffffffffu, h[k], 1);

    size_t BS = (size_t)B * 16;

    if (dir == 0) {
        float impv[16];
#pragma unroll
        for (int s = 0; s < 16; s++) {
            float xt = sXV[s * 128 + pair];
            float mt = sMV[s * 128 + pair];
            impv[s] = fmaf(mt, xt - hs[s], hs[s]);
        }
        float4* o4 = reinterpret_cast<float4*>(out + (size_t)b * 16);
#pragma unroll
        for (int i = 0; i < 4; i++)
            o4[i] = make_float4(impv[4 * i], impv[4 * i + 1], impv[4 * i + 2], impv[4 * i + 3]);
    } else {
        float lat[16];
#pragma unroll
        for (int l = 0; l < 16; l++) lat[l] = dotN<16>(sFcW + l * 16, hs, sFcB[l]);
        float4* l4 = reinterpret_cast<float4*>(out + 2 * BS + (size_t)b * 16);
#pragma unroll
        for (int i = 0; i < 4; i++)
            l4[i] = make_float4(lat[4 * i], lat[4 * i + 1], lat[4 * i + 2], lat[4 * i + 3]);
    }
}

// ===========================================================================
// Discriminator: scalar, one sample per thread. 'f' gate dead -> 3 gates.
// i/o gate weights+biases pre-halved in smem so sigmoid(x)=0.5*tanh(x/2)+0.5
// needs no extra multiply. Row layout per layer: [i-rows | g-rows | o-rows].
// ===========================================================================
__global__ void __launch_bounds__(256)
disc_kernel(const float* __restrict__ W0, const float* __restrict__ b0,
            const float* __restrict__ W1, const float* __restrict__ b1,
            const float* __restrict__ W2, const float* __restrict__ b2,
            const float* __restrict__ W3, const float* __restrict__ b3,
            const float* __restrict__ W4, const float* __restrict__ b4,
            const float* __restrict__ dow, const float* __restrict__ dob,
            float* out, int BS)
{
    __shared__ __align__(16) float sW1[1536], sW4[1536];   // [48][32], [96][16]
    __shared__ __align__(16) float sW2[384],  sW3[384];    // [24][16], [48][8]
    __shared__ __align__(16) float sW0[96], sB0[96], sB4[96];
    __shared__ __align__(16) float sB1[48], sB3[48], sB2[24], sDow[32];
    __shared__ float sRec[16];
    __shared__ float sDob;

    const int NT = 256;
    int tid = threadIdx.x;

    // pack: slot s -> original gate row; scale i (t==0) and o (t==2) by 0.5
    for (int i = tid; i < 1536; i += NT) {
        { int j = i >> 5, k = i & 31; int t = j >> 4;            // L1: 16 rows/gate
          int row = j + ((t > 0) ? 16 : 0);                       // skip f block
          float sc = (t == 1) ? 1.0f : 0.5f;
          sW1[i] = sc * W1[row * 32 + k]; }
        { int j = i >> 4, k = i & 15; int t = j >> 5;            // L4: 32 rows/gate
          int row = j + ((t > 0) ? 32 : 0);
          float sc = (t == 1) ? 1.0f : 0.5f;
          sW4[i] = sc * W4[row * 16 + k]; }
    }
    for (int i = tid; i < 384; i += NT) {
        { int j = i >> 4, k = i & 15; int t = j >> 3;            // L2: 8 rows/gate
          int row = j + ((t > 0) ? 8 : 0);
          float sc = (t == 1) ? 1.0f : 0.5f;
          sW2[i] = sc * W2[row * 16 + k]; }
        { int j = i >> 3, k = i & 7; int t = j >> 4;             // L3: 16 rows/gate
          int row = j + ((t > 0) ? 16 : 0);
          float sc = (t == 1) ? 1.0f : 0.5f;
          sW3[i] = sc * W3[row * 8 + k]; }
    }
    for (int i = tid; i < 96; i += NT) {
        int t = i >> 5; int row = i + ((t > 0) ? 32 : 0);
        float sc = (t == 1) ? 1.0f : 0.5f;
        sW0[i] = sc * W0[row];
        sB0[i] = sc * b0[row];
        sB4[i] = sc * b4[row];
    }
    if (tid < 48) {
        int t = tid >> 4; int row = tid + ((t > 0) ? 16 : 0);
        float sc = (t == 1) ? 1.0f : 0.5f;
        sB1[tid] = sc * b1[row];
        sB3[tid] = sc * b3[row];
    }
    if (tid < 24) {
        int t = tid >> 3; int row = tid + ((t > 0) ? 8 : 0);
        float sc = (t == 1) ? 1.0f : 0.5f;
        sB2[tid] = sc * b2[row];
    }
    if (tid < 32) sDow[tid] = dow[tid];
    if (tid < 16) sRec[tid] = g_dec_recon[tid];
    if (tid == 0) sDob = dob[0];
    __syncthreads();

    int idx = blockIdx.x * NT + tid;
    if (idx >= BS) return;

    float a = out[idx];   // imputed

    // unit: si = 0.5*tanh(hi)+0.5 (hi = pre-halved i dot); similarly o.
#define UNIT(hi, gg, ho, dst)                                     \
    {                                                             \
        float si = fmaf(0.5f, tanh_a(hi), 0.5f);                  \
        float so = fmaf(0.5f, tanh_a(ho), 0.5f);                  \
        float cc = si * tanh_a(gg);                               \
        dst = so * tanh_a(cc);                                    \
    }

    // L0: 1 -> 32
    float v0[32];
#pragma unroll
    for (int j = 0; j < 32; j++) {
        float hi = fmaf(a, sW0[j],      sB0[j]);
        float gg = fmaf(a, sW0[32 + j], sB0[32 + j]);
        float ho = fmaf(a, sW0[64 + j], sB0[64 + j]);
        UNIT(hi, gg, ho, v0[j]);
    }
    // L1: 32 -> 16
    float v1[16];
#pragma unroll
    for (int j = 0; j < 16; j++) {
        float hi = dotN<32>(sW1 + j * 32,        v0, sB1[j]);
        float gg = dotN<32>(sW1 + (16 + j) * 32, v0, sB1[16 + j]);
        float ho = dotN<32>(sW1 + (32 + j) * 32, v0, sB1[32 + j]);
        UNIT(hi, gg, ho, v1[j]);
    }
    // L2: 16 -> 8
    float v2[8];
#pragma unroll
    for (int j = 0; j < 8; j++) {
        float hi = dotN<16>(sW2 + j * 16,       v1, sB2[j]);
        float gg = dotN<16>(sW2 + (8 + j) * 16, v1, sB2[8 + j]);
        float ho = dotN<16>(sW2 + (16 + j) * 16, v1, sB2[16 + j]);
        UNIT(hi, gg, ho, v2[j]);
    }
    // L3: 8 -> 16
    float v3[16];
#pragma unroll
    for (int j = 0; j < 16; j++) {
        float hi = dotN<8>(sW3 + j * 8,        v2, sB3[j]);
        float gg = dotN<8>(sW3 + (16 + j) * 8, v2, sB3[16 + j]);
        float ho = dotN<8>(sW3 + (32 + j) * 8, v2, sB3[32 + j]);
        UNIT(hi, gg, ho, v3[j]);
    }
    // L4: 16 -> 32, fused with final dot
    float r = sDob;
#pragma unroll
    for (int j = 0; j < 32; j++) {
        float hi = dotN<16>(sW4 + j * 16,        v3, sB4[j]);
        float gg = dotN<16>(sW4 + (32 + j) * 16, v3, sB4[32 + j]);
        float ho = dotN<16>(sW4 + (64 + j) * 16, v3, sB4[64 + j]);
        float v4;
        UNIT(hi, gg, ho, v4);
        r = fmaf(v4, sDow[j], r);
    }
#undef UNIT

    out[(size_t)BS + idx] = r;
    out[3 * (size_t)BS + idx] = sRec[idx & 15];
}

// ---------------------------------------------------------------------------
extern "C" void kernel_launch(void* const* d_in, const int* in_sizes, int n_in,
                              void* d_out, int out_size)
{
    const float* values = (const float*)d_in[0];
    const int*   masks  = (const int*)  d_in[1];
    const float* gfW = (const float*)d_in[2];
    const float* gfU = (const float*)d_in[3];
    const float* gfb = (const float*)d_in[4];
    const float* gbW = (const float*)d_in[5];
    const float* gbU = (const float*)d_in[6];
    const float* gbb = (const float*)d_in[7];
    const float* impW = (const float*)d_in[8];
    const float* impB = (const float*)d_in[9];
    const float* fcW  = (const float*)d_in[10];
    const float* fcB  = (const float*)d_in[11];
    const float* dWih = (const float*)d_in[12];
    const float* dWhh = (const float*)d_in[13];
    const float* db_  = (const float*)d_in[14];
    const float* dOW  = (const float*)d_in[15];
    const float* dOB  = (const float*)d_in[16];
    const float* dow  = (const float*)d_in[17];
    const float* dob  = (const float*)d_in[18];
    const float* W0 = (const float*)d_in[19]; const float* b0 = (const float*)d_in[20];
    const float* W1 = (const float*)d_in[21]; const float* b1 = (const float*)d_in[22];
    const float* W2 = (const float*)d_in[23]; const float* b2 = (const float*)d_in[24];
    const float* W3 = (const float*)d_in[25]; const float* b3 = (const float*)d_in[26];
    const float* W4 = (const float*)d_in[27]; const float* b4 = (const float*)d_in[28];

    float* out = (float*)d_out;
    int B  = in_sizes[0] / 16;     // 32768
    int BS = B * 16;               // 524288

    gen_kernel<<<B / 128 + 1, 256>>>(values, masks, gfU, gfW, gfb, gbU, gbW, gbb,
                                     impW, impB, fcW, fcB,
                                     dWih, dWhh, db_, dOW, dOB, out, B);
    disc_kernel<<<(BS + 255) / 256, 256>>>(W0, b0, W1, b1, W2, b2, W3, b3, W4, b4,
                                           dow, dob, out, BS);
}

// round 7
// speedup vs baseline: 4.0113x; 3.7130x over previous
#include <cuda_runtime.h>
#include <cuda_bf16.h>
#include <cstdint>

// out layout (fp32): [0,BS) imputed | [BS,2BS) disc | [2BS,3BS) latent | [3BS,4BS) recon
// BS = B*16

#define S16 16
#define H16 16

__device__ float g_init[64];       // h_f0[16], c_f0[16], h_b0[16], c_b0[16]
__device__ float g_dec_recon[16];  // reconstructed[s] (batch-independent)

// ---- activations ----------------------------------------------------------
__device__ __forceinline__ float fast_ex2(float x) {
    float y; asm("ex2.approx.f32 %0, %1;" : "=f"(y) : "f"(x)); return y;
}
__device__ __forceinline__ float fast_rcp(float x) {
    float y; asm("rcp.approx.f32 %0, %1;" : "=f"(y) : "f"(x)); return y;
}
__device__ __forceinline__ float sigmoidf_(float x) {
    return fast_rcp(1.0f + fast_ex2(-1.4426950408889634f * x));
}
__device__ __forceinline__ float tanhf_(float x) {
    float t = fast_ex2(-2.8853901f * x);
    return fmaf(2.0f, fast_rcp(1.0f + t), -1.0f);
}
// fast (feedforward disc only; proven rel_err ~2.7e-6)
__device__ __forceinline__ float tanh_a(float x) {
    float y; asm("tanh.approx.f32 %0, %1;" : "=f"(y) : "f"(x)); return y;
}

// dot over N (multiple of 4) smem weights (16B-aligned rows) x register vector
template <int N>
__device__ __forceinline__ float dotN_acc(const float* __restrict__ w,
                                          const float* __restrict__ v, float acc) {
#pragma unroll
    for (int k = 0; k < N; k += 4) {
        float4 wv = *reinterpret_cast<const float4*>(w + k);
        acc = fmaf(v[k + 0], wv.x, acc);
        acc = fmaf(v[k + 1], wv.y, acc);
        acc = fmaf(v[k + 2], wv.z, acc);
        acc = fmaf(v[k + 3], wv.w, acc);
    }
    return acc;
}

// one LSTM cell step, H=16, scalar input cc. h,c live in registers.
__device__ __forceinline__ void lstm_step16(float h[16], float c[16], float cc,
                                            const float* __restrict__ U,     // [64][16] smem
                                            const float* __restrict__ wih,   // [64] smem
                                            const float* __restrict__ bias)  // [64] smem
{
    float hn[16];
#pragma unroll
    for (int j = 0; j < 16; j++) {
        float gi = dotN_acc<16>(U + (j +  0) * 16, h, fmaf(cc, wih[j +  0], bias[j +  0]));
        float gf = dotN_acc<16>(U + (j + 16) * 16, h, fmaf(cc, wih[j + 16], bias[j + 16]));
        float gg = dotN_acc<16>(U + (j + 32) * 16, h, fmaf(cc, wih[j + 32], bias[j + 32]));
        float go = dotN_acc<16>(U + (j + 48) * 16, h, fmaf(cc, wih[j + 48], bias[j + 48]));
        float cn = fmaf(sigmoidf_(gf), c[j], sigmoidf_(gi) * tanhf_(gg));
        c[j] = cn;
        hn[j] = sigmoidf_(go) * tanhf_(cn);
    }
#pragma unroll
    for (int j = 0; j < 16; j++) h[j] = hn[j];
}

// ---------------------------------------------------------------------------
// Kernel 1 (VERBATIM round-1): batch-independent precompute. 1 block, 32 thr.
// ---------------------------------------------------------------------------
__global__ void setup_kernel(const float* __restrict__ gfW, const float* __restrict__ gfb,
                             const float* __restrict__ gbW, const float* __restrict__ gbb,
                             const float* __restrict__ dWih, const float* __restrict__ dWhh,
                             const float* __restrict__ db,
                             const float* __restrict__ dOW, const float* __restrict__ dOB)
{
    int tid = threadIdx.x;
    __shared__ float shd[16], scd[16];

    if (tid < 16) {
        {
            float gi = fmaf(128.0f, gfW[tid +  0], gfb[tid +  0]);
            float gg = fmaf(128.0f, gfW[tid + 32], gfb[tid + 32]);
            float go = fmaf(128.0f, gfW[tid + 48], gfb[tid + 48]);
            float c = sigmoidf_(gi) * tanhf_(gg);
            float h = sigmoidf_(go) * tanhf_(c);
            g_init[tid] = h;  g_init[16 + tid] = c;
        }
        {
            float gi = fmaf(-128.0f, gbW[tid +  0], gbb[tid +  0]);
            float gg = fmaf(-128.0f, gbW[tid + 32], gbb[tid + 32]);
            float go = fmaf(-128.0f, gbW[tid + 48], gbb[tid + 48]);
            float c = sigmoidf_(gi) * tanhf_(gg);
            float h = sigmoidf_(go) * tanhf_(c);
            g_init[32 + tid] = h;  g_init[48 + tid] = c;
        }
        {
            float si = db[tid], sg = db[tid + 32], so = db[tid + 48];
            for (int k = 0; k < 16; k++) {
                si = fmaf(128.0f, dWih[(tid +  0) * 16 + k], si);
                sg = fmaf(128.0f, dWih[(tid + 32) * 16 + k], sg);
                so = fmaf(128.0f, dWih[(tid + 48) * 16 + k], so);
            }
            float c = sigmoidf_(si) * tanhf_(sg);
            float h = sigmoidf_(so) * tanhf_(c);
            shd[tid] = h; scd[tid] = c;
        }
    }
    __syncthreads();

    for (int s = 0; s < S16; s++) {
        float gi = 0.f, gf = 0.f, gg = 0.f, go = 0.f;
        if (tid < 16) {
            gi = db[tid]; gf = db[tid + 16]; gg = db[tid + 32]; go = db[tid + 48];
            for (int k = 0; k < 16; k++) {
                float xk = scd[k], hk = shd[k];
                gi = fmaf(xk, dWih[(tid +  0) * 16 + k], fmaf(hk, dWhh[(tid +  0) * 16 + k], gi));
                gf = fmaf(xk, dWih[(tid + 16) * 16 + k], fmaf(hk, dWhh[(tid + 16) * 16 + k], gf));
                gg = fmaf(xk, dWih[(tid + 32) * 16 + k], fmaf(hk, dWhh[(tid + 32) * 16 + k], gg));
                go = fmaf(xk, dWih[(tid + 48) * 16 + k], fmaf(hk, dWhh[(tid + 48) * 16 + k], go));
            }
        }
        __syncthreads();
        if (tid < 16) {
            float c = fmaf(sigmoidf_(gf), scd[tid], sigmoidf_(gi) * tanhf_(gg));
            float h = sigmoidf_(go) * tanhf_(c);
            scd[tid] = c; shd[tid] = h;
        }
        __syncthreads();
        if (tid == 0) {
            float acc = dOB[0];
            for (int k = 0; k < 16; k++) acc = fmaf(shd[k], dOW[k], acc);
            g_dec_recon[s] = acc;
        }
        __syncthreads();
    }
}

// ---------------------------------------------------------------------------
// Kernel 2 (VERBATIM round-1): generator. One thread per batch row.
// ---------------------------------------------------------------------------
__global__ void __launch_bounds__(128)
gen_kernel(const float* __restrict__ values, const int* __restrict__ masks,
           const float* __restrict__ gfU, const float* __restrict__ gfW, const float* __restrict__ gfb,
           const float* __restrict__ gbU, const float* __restrict__ gbW, const float* __restrict__ gbb,
           const float* __restrict__ impW, const float* __restrict__ impB,
           const float* __restrict__ fcW, const float* __restrict__ fcB,
           float* __restrict__ out, int B)
{
    __shared__ __align__(16) float sUf[1024], sUb[1024];
    __shared__ __align__(16) float sWf[64], sWb[64], sBf[64], sBb[64];
    __shared__ __align__(16) float sImpW[16], sFcW[256], sFcB[16], sInit[64];

    int tid = threadIdx.x;
    for (int i = tid; i < 1024; i += 128) { sUf[i] = gfU[i]; sUb[i] = gbU[i]; }
    for (int i = tid; i < 64; i += 128) {
        sWf[i] = gfW[i]; sWb[i] = gbW[i]; sBf[i] = gfb[i]; sBb[i] = gbb[i];
        sInit[i] = g_init[i];
    }
    for (int i = tid; i < 256; i += 128) sFcW[i] = fcW[i];
    if (tid < 16) { sImpW[tid] = impW[tid]; sFcB[tid] = fcB[tid]; }
    __syncthreads();

    int b = blockIdx.x * 128 + tid;
    if (b >= B) return;
    float impb = __ldg(impB);

    const float* vrow = values + (size_t)b * S16;
    const int*   mrow = masks  + (size_t)b * S16;

    float hf[16], cf[16], hb[16], cb[16];
#pragma unroll
    for (int k = 0; k < 16; k++) {
        hf[k] = sInit[k]; cf[k] = sInit[16 + k];
        hb[k] = sInit[32 + k]; cb[k] = sInit[48 + k];
    }

#pragma unroll 1
    for (int t = 0; t < S16; t++) {
        float xt = __ldg(vrow + t);
        float mt = (float)__ldg(mrow + t);
        float df = dotN_acc<16>(sImpW, hf, impb);
        float db = dotN_acc<16>(sImpW, hb, impb);
        float ccf = fmaf(mt, df - xt, xt);
        float ccb = fmaf(mt, db - xt, xt);
        lstm_step16(hf, cf, ccf, sUf, sWf, sBf);
        lstm_step16(hb, cb, ccb, sUb, sWb, sBb);
    }

    float h[16];
#pragma unroll
    for (int k = 0; k < 16; k++) h[k] = hf[k] + hb[k];

    size_t BS = (size_t)B * S16;

    float impv[16];
#pragma unroll
    for (int s = 0; s < 16; s++) {
        float xt = __ldg(vrow + s);
        float mt = (float)__ldg(mrow + s);
        impv[s] = fmaf(mt, xt - h[s], h[s]);
    }
    float4* o4 = reinterpret_cast<float4*>(out + (size_t)b * 16);
#pragma unroll
    for (int i = 0; i < 4; i++)
        o4[i] = make_float4(impv[4 * i], impv[4 * i + 1], impv[4 * i + 2], impv[4 * i + 3]);

    float lat[16];
#pragma unroll
    for (int l = 0; l < 16; l++) lat[l] = dotN_acc<16>(sFcW + l * 16, h, sFcB[l]);
    float4* l4 = reinterpret_cast<float4*>(out + 2 * BS + (size_t)b * 16);
#pragma unroll
    for (int i = 0; i < 4; i++)
        l4[i] = make_float4(lat[4 * i], lat[4 * i + 1], lat[4 * i + 2], lat[4 * i + 3]);
}

// ---------------------------------------------------------------------------
// Kernel 3 (VERBATIM round-5): discriminator, one sample per thread.
// 'f' gate dead; i/o weights pre-halved so sigmoid = 0.5*tanh(x/2)+0.5.
// ---------------------------------------------------------------------------
__global__ void __launch_bounds__(256)
disc_kernel(const float* __restrict__ W0, const float* __restrict__ b0,
            const float* __restrict__ W1, const float* __restrict__ b1,
            const float* __restrict__ W2, const float* __restrict__ b2,
            const float* __restrict__ W3, const float* __restrict__ b3,
            const float* __restrict__ W4, const float* __restrict__ b4,
            const float* __restrict__ dow, const float* __restrict__ dob,
            float* out, int BS)
{
    __shared__ __align__(16) float sW1[1536], sW4[1536];   // [48][32], [96][16]
    __shared__ __align__(16) float sW2[384],  sW3[384];    // [24][16], [48][8]
    __shared__ __align__(16) float sW0[96], sB0[96], sB4[96];
    __shared__ __align__(16) float sB1[48], sB3[48], sB2[24], sDow[32];
    __shared__ float sRec[16];
    __shared__ float sDob;

    const int NT = 256;
    int tid = threadIdx.x;

    for (int i = tid; i < 1536; i += NT) {
        { int j = i >> 5, k = i & 31; int t = j >> 4;
          int row = j + ((t > 0) ? 16 : 0);
          float sc = (t == 1) ? 1.0f : 0.5f;
          sW1[i] = sc * W1[row * 32 + k]; }
        { int j = i >> 4, k = i & 15; int t = j >> 5;
          int row = j + ((t > 0) ? 32 : 0);
          float sc = (t == 1) ? 1.0f : 0.5f;
          sW4[i] = sc * W4[row * 16 + k]; }
    }
    for (int i = tid; i < 384; i += NT) {
        { int j = i >> 4, k = i & 15; int t = j >> 3;
          int row = j + ((t > 0) ? 8 : 0);
          float sc = (t == 1) ? 1.0f : 0.5f;
          sW2[i] = sc * W2[row * 16 + k]; }
        { int j = i >> 3, k = i & 7; int t = j >> 4;
          int row = j + ((t > 0) ? 16 : 0);
          float sc = (t == 1) ? 1.0f : 0.5f;
          sW3[i] = sc * W3[row * 8 + k]; }
    }
    for (int i = tid; i < 96; i += NT) {
        int t = i >> 5; int row = i + ((t > 0) ? 32 : 0);
        float sc = (t == 1) ? 1.0f : 0.5f;
        sW0[i] = sc * W0[row];
        sB0[i] = sc * b0[row];
        sB4[i] = sc * b4[row];
    }
    if (tid < 48) {
        int t = tid >> 4; int row = tid + ((t > 0) ? 16 : 0);
        float sc = (t == 1) ? 1.0f : 0.5f;
        sB1[tid] = sc * b1[row];
        sB3[tid] = sc * b3[row];
    }
    if (tid < 24) {
        int t = tid >> 3; int row = tid + ((t > 0) ? 8 : 0);
        float sc = (t == 1) ? 1.0f : 0.5f;
        sB2[tid] = sc * b2[row];
    }
    if (tid < 32) sDow[tid] = dow[tid];
    if (tid < 16) sRec[tid] = g_dec_recon[tid];
    if (tid == 0) sDob = dob[0];
    __syncthreads();

    int idx = blockIdx.x * NT + tid;
    if (idx >= BS) return;

    float a = out[idx];   // imputed

#define UNIT(hi, gg, ho, dst)                                     \
    {                                                             \
        float si = fmaf(0.5f, tanh_a(hi), 0.5f);                  \
        float so = fmaf(0.5f, tanh_a(ho), 0.5f);                  \
        float cc = si * tanh_a(gg);                               \
        dst = so * tanh_a(cc);                                    \
    }

    float v0[32];
#pragma unroll
    for (int j = 0; j < 32; j++) {
        float hi = fmaf(a, sW0[j],      sB0[j]);
        float gg = fmaf(a, sW0[32 + j], sB0[32 + j]);
        float ho = fmaf(a, sW0[64 + j], sB0[64 + j]);
        UNIT(hi, gg, ho, v0[j]);
    }
    float v1[16];
#pragma unroll
    for (int j = 0; j < 16; j++) {
        float hi = dotN_acc<32>(sW1 + j * 32,        v0, sB1[j]);
        float gg = dotN_acc<32>(sW1 + (16 + j) * 32, v0, sB1[16 + j]);
        float ho = dotN_acc<32>(sW1 + (32 + j) * 32, v0, sB1[32 + j]);
        UNIT(hi, gg, ho, v1[j]);
    }
    float v2[8];
#pragma unroll
    for (int j = 0; j < 8; j++) {
        float hi = dotN_acc<16>(sW2 + j * 16,        v1, sB2[j]);
        float gg = dotN_acc<16>(sW2 + (8 + j) * 16,  v1, sB2[8 + j]);
        float ho = dotN_acc<16>(sW2 + (16 + j) * 16, v1, sB2[16 + j]);
        UNIT(hi, gg, ho, v2[j]);
    }
    float v3[16];
#pragma unroll
    for (int j = 0; j < 16; j++) {
        float hi = dotN_acc<8>(sW3 + j * 8,        v2, sB3[j]);
        float gg = dotN_acc<8>(sW3 + (16 + j) * 8, v2, sB3[16 + j]);
        float ho = dotN_acc<8>(sW3 + (32 + j) * 8, v2, sB3[32 + j]);
        UNIT(hi, gg, ho, v3[j]);
    }
    float r = sDob;
#pragma unroll
    for (int j = 0; j < 32; j++) {
        float hi = dotN_acc<16>(sW4 + j * 16,        v3, sB4[j]);
        float gg = dotN_acc<16>(sW4 + (32 + j) * 16, v3, sB4[32 + j]);
        float ho = dotN_acc<16>(sW4 + (64 + j) * 16, v3, sB4[64 + j]);
        float v4;
        UNIT(hi, gg, ho, v4);
        r = fmaf(v4, sDow[j], r);
    }
#undef UNIT

    out[(size_t)BS + idx] = r;
    out[3 * (size_t)BS + idx] = sRec[idx & 15];
}

// ---------------------------------------------------------------------------
extern "C" void kernel_launch(void* const* d_in, const int* in_sizes, int n_in,
                              void* d_out, int out_size)
{
    const float* values = (const float*)d_in[0];
    const int*   masks  = (const int*)  d_in[1];
    const float* gfW = (const float*)d_in[2];
    const float* gfU = (const float*)d_in[3];
    const float* gfb = (const float*)d_in[4];
    const float* gbW = (const float*)d_in[5];
    const float* gbU = (const float*)d_in[6];
    const float* gbb = (const float*)d_in[7];
    const float* impW = (const float*)d_in[8];
    const float* impB = (const float*)d_in[9];
    const float* fcW  = (const float*)d_in[10];
    const float* fcB  = (const float*)d_in[11];
    const float* dWih = (const float*)d_in[12];
    const float* dWhh = (const float*)d_in[13];
    const float* db_  = (const float*)d_in[14];
    const float* dOW  = (const float*)d_in[15];
    const float* dOB  = (const float*)d_in[16];
    const float* dow  = (const float*)d_in[17];
    const float* dob  = (const float*)d_in[18];
    const float* W0 = (const float*)d_in[19]; const float* b0 = (const float*)d_in[20];
    const float* W1 = (const float*)d_in[21]; const float* b1 = (const float*)d_in[22];
    const float* W2 = (const float*)d_in[23]; const float* b2 = (const float*)d_in[24];
    const float* W3 = (const float*)d_in[25]; const float* b3 = (const float*)d_in[26];
    const float* W4 = (const float*)d_in[27]; const float* b4 = (const float*)d_in[28];

    float* out = (float*)d_out;
    int B  = in_sizes[0] / 16;     // 32768
    int BS = B * 16;               // 524288

    setup_kernel<<<1, 32>>>(gfW, gfb, gbW, gbb, dWih, dWhh, db_, dOW, dOB);
    gen_kernel<<<(B + 127) / 128, 128>>>(values, masks, gfU, gfW, gfb,
                                         gbU, gbW, gbb, impW, impB, fcW, fcB, out, B);
    disc_kernel<<<(BS + 255) / 256, 256>>>(W0, b0, W1, b1, W2, b2, W3, b3, W4, b4,
                                           dow, dob, out, BS);
}

// round 8
// speedup vs baseline: 4.0937x; 1.0205x over previous
#include <cuda_runtime.h>
#include <cuda_bf16.h>
#include <cstdint>

// out layout (fp32): [0,BS) imputed | [BS,2BS) disc | [2BS,3BS) latent | [3BS,4BS) recon
// BS = B*16

#define S16 16
#define H16 16

__device__ float g_init[64];       // h_f0[16], c_f0[16], h_b0[16], c_b0[16]
__device__ float g_dec_recon[16];  // reconstructed[s] (batch-independent)

// ---- activations ----------------------------------------------------------
__device__ __forceinline__ float fast_ex2(float x) {
    float y; asm("ex2.approx.f32 %0, %1;" : "=f"(y) : "f"(x)); return y;
}
__device__ __forceinline__ float fast_rcp(float x) {
    float y; asm("rcp.approx.f32 %0, %1;" : "=f"(y) : "f"(x)); return y;
}
__device__ __forceinline__ float sigmoidf_(float x) {
    return fast_rcp(1.0f + fast_ex2(-1.4426950408889634f * x));
}
__device__ __forceinline__ float tanhf_(float x) {
    float t = fast_ex2(-2.8853901f * x);
    return fmaf(2.0f, fast_rcp(1.0f + t), -1.0f);
}
// fast (feedforward disc only; proven rel_err ~2.7e-6)
__device__ __forceinline__ float tanh_a(float x) {
    float y; asm("tanh.approx.f32 %0, %1;" : "=f"(y) : "f"(x)); return y;
}

// dot over N (multiple of 4) smem weights (16B-aligned rows) x register vector
template <int N>
__device__ __forceinline__ float dotN_acc(const float* __restrict__ w,
                                          const float* __restrict__ v, float acc) {
#pragma unroll
    for (int k = 0; k < N; k += 4) {
        float4 wv = *reinterpret_cast<const float4*>(w + k);
        acc = fmaf(v[k + 0], wv.x, acc);
        acc = fmaf(v[k + 1], wv.y, acc);
        acc = fmaf(v[k + 2], wv.z, acc);
        acc = fmaf(v[k + 3], wv.w, acc);
    }
    return acc;
}

// one LSTM cell step, H=16, scalar input cc. h,c live in registers.
__device__ __forceinline__ void lstm_step16(float h[16], float c[16], float cc,
                                            const float* __restrict__ U,     // [64][16] smem
                                            const float* __restrict__ wih,   // [64] smem
                                            const float* __restrict__ bias)  // [64] smem
{
    float hn[16];
#pragma unroll
    for (int j = 0; j < 16; j++) {
        float gi = dotN_acc<16>(U + (j +  0) * 16, h, fmaf(cc, wih[j +  0], bias[j +  0]));
        float gf = dotN_acc<16>(U + (j + 16) * 16, h, fmaf(cc, wih[j + 16], bias[j + 16]));
        float gg = dotN_acc<16>(U + (j + 32) * 16, h, fmaf(cc, wih[j + 32], bias[j + 32]));
        float go = dotN_acc<16>(U + (j + 48) * 16, h, fmaf(cc, wih[j + 48], bias[j + 48]));
        float cn = fmaf(sigmoidf_(gf), c[j], sigmoidf_(gi) * tanhf_(gg));
        c[j] = cn;
        hn[j] = sigmoidf_(go) * tanhf_(cn);
    }
#pragma unroll
    for (int j = 0; j < 16; j++) h[j] = hn[j];
}

// ---------------------------------------------------------------------------
// Kernel 1: batch-independent precompute. 1 block, 64 threads.
// CHANGED vs R7: decoder weights staged into smem once (the 31us was global-
// latency in the serial loop); recurrence math identical.
// ---------------------------------------------------------------------------
__global__ void __launch_bounds__(64)
setup_kernel(const float* __restrict__ gfW, const float* __restrict__ gfb,
             const float* __restrict__ gbW, const float* __restrict__ gbb,
             const float* __restrict__ dWih, const float* __restrict__ dWhh,
             const float* __restrict__ db,
             const float* __restrict__ dOW, const float* __restrict__ dOB)
{
    __shared__ __align__(16) float sWih[1024], sWhh[1024];
    __shared__ float sb[64], sOW[16], shd[16], scd[16], sgat[64];

    int tid = threadIdx.x;
    for (int i = tid; i < 1024; i += 64) { sWih[i] = dWih[i]; sWhh[i] = dWhh[i]; }
    sb[tid] = db[tid];
    if (tid < 16) sOW[tid] = dOW[tid];
    __syncthreads();

    if (tid < 16) {
        // generator fwd init (x=+128, h=c=0)
        {
            float gi = fmaf(128.0f, gfW[tid +  0], gfb[tid +  0]);
            float gg = fmaf(128.0f, gfW[tid + 32], gfb[tid + 32]);
            float go = fmaf(128.0f, gfW[tid + 48], gfb[tid + 48]);
            float c = sigmoidf_(gi) * tanhf_(gg);
            float h = sigmoidf_(go) * tanhf_(c);
            g_init[tid] = h;  g_init[16 + tid] = c;
        }
        // generator bwd init (x=-128)
        {
            float gi = fmaf(-128.0f, gbW[tid +  0], gbb[tid +  0]);
            float gg = fmaf(-128.0f, gbW[tid + 32], gbb[tid + 32]);
            float go = fmaf(-128.0f, gbW[tid + 48], gbb[tid + 48]);
            float c = sigmoidf_(gi) * tanhf_(gg);
            float h = sigmoidf_(go) * tanhf_(c);
            g_init[32 + tid] = h;  g_init[48 + tid] = c;
        }
        // decoder init (x = full(128,16), h=c=0)
        {
            float si = sb[tid], sg = sb[tid + 32], so = sb[tid + 48];
#pragma unroll
            for (int k = 0; k < 16; k++) {
                si = fmaf(128.0f, sWih[(tid +  0) * 16 + k], si);
                sg = fmaf(128.0f, sWih[(tid + 32) * 16 + k], sg);
                so = fmaf(128.0f, sWih[(tid + 48) * 16 + k], so);
            }
            float c = sigmoidf_(si) * tanhf_(sg);
            float h = sigmoidf_(so) * tanhf_(c);
            shd[tid] = h; scd[tid] = c;
        }
    }
    __syncthreads();

    for (int s = 0; s < S16; s++) {
        {
            float acc = sb[tid];
#pragma unroll
            for (int k = 0; k < 16; k++)
                acc = fmaf(scd[k], sWih[tid * 16 + k], fmaf(shd[k], sWhh[tid * 16 + k], acc));
            sgat[tid] = acc;
        }
        __syncthreads();
        if (tid < 16) {
            float c = fmaf(sigmoidf_(sgat[tid + 16]), scd[tid],
                           sigmoidf_(sgat[tid]) * tanhf_(sgat[tid + 32]));
            float h = sigmoidf_(sgat[tid + 48]) * tanhf_(c);
            scd[tid] = c; shd[tid] = h;
        }
        __syncthreads();
        if (tid == 0) {
            float acc = dOB[0];
#pragma unroll
            for (int k = 0; k < 16; k++) acc = fmaf(shd[k], sOW[k], acc);
            g_dec_recon[s] = acc;
        }
        __syncthreads();
    }
}

// ---------------------------------------------------------------------------
// Kernel 2 (VERBATIM R7): generator. One thread per batch row.
// ---------------------------------------------------------------------------
__global__ void __launch_bounds__(128)
gen_kernel(const float* __restrict__ values, const int* __restrict__ masks,
           const float* __restrict__ gfU, const float* __restrict__ gfW, const float* __restrict__ gfb,
           const float* __restrict__ gbU, const float* __restrict__ gbW, const float* __restrict__ gbb,
           const float* __restrict__ impW, const float* __restrict__ impB,
           const float* __restrict__ fcW, const float* __restrict__ fcB,
           float* __restrict__ out, int B)
{
    __shared__ __align__(16) float sUf[1024], sUb[1024];
    __shared__ __align__(16) float sWf[64], sWb[64], sBf[64], sBb[64];
    __shared__ __align__(16) float sImpW[16], sFcW[256], sFcB[16], sInit[64];

    int tid = threadIdx.x;
    for (int i = tid; i < 1024; i += 128) { sUf[i] = gfU[i]; sUb[i] = gbU[i]; }
    for (int i = tid; i < 64; i += 128) {
        sWf[i] = gfW[i]; sWb[i] = gbW[i]; sBf[i] = gfb[i]; sBb[i] = gbb[i];
        sInit[i] = g_init[i];
    }
    for (int i = tid; i < 256; i += 128) sFcW[i] = fcW[i];
    if (tid < 16) { sImpW[tid] = impW[tid]; sFcB[tid] = fcB[tid]; }
    __syncthreads();

    int b = blockIdx.x * 128 + tid;
    if (b >= B) return;
    float impb = __ldg(impB);

    const float* vrow = values + (size_t)b * S16;
    const int*   mrow = masks  + (size_t)b * S16;

    float hf[16], cf[16], hb[16], cb[16];
#pragma unroll
    for (int k = 0; k < 16; k++) {
        hf[k] = sInit[k]; cf[k] = sInit[16 + k];
        hb[k] = sInit[32 + k]; cb[k] = sInit[48 + k];
    }

#pragma unroll 1
    for (int t = 0; t < S16; t++) {
        float xt = __ldg(vrow + t);
        float mt = (float)__ldg(mrow + t);
        float df = dotN_acc<16>(sImpW, hf, impb);
        float db = dotN_acc<16>(sImpW, hb, impb);
        float ccf = fmaf(mt, df - xt, xt);
        float ccb = fmaf(mt, db - xt, xt);
        lstm_step16(hf, cf, ccf, sUf, sWf, sBf);
        lstm_step16(hb, cb, ccb, sUb, sWb, sBb);
    }

    float h[16];
#pragma unroll
    for (int k = 0; k < 16; k++) h[k] = hf[k] + hb[k];

    size_t BS = (size_t)B * S16;

    float impv[16];
#pragma unroll
    for (int s = 0; s < 16; s++) {
        float xt = __ldg(vrow + s);
        float mt = (float)__ldg(mrow + s);
        impv[s] = fmaf(mt, xt - h[s], h[s]);
    }
    float4* o4 = reinterpret_cast<float4*>(out + (size_t)b * 16);
#pragma unroll
    for (int i = 0; i < 4; i++)
        o4[i] = make_float4(impv[4 * i], impv[4 * i + 1], impv[4 * i + 2], impv[4 * i + 3]);

    float lat[16];
#pragma unroll
    for (int l = 0; l < 16; l++) lat[l] = dotN_acc<16>(sFcW + l * 16, h, sFcB[l]);
    float4* l4 = reinterpret_cast<float4*>(out + 2 * BS + (size_t)b * 16);
#pragma unroll
    for (int i = 0; i < 4; i++)
        l4[i] = make_float4(lat[4 * i], lat[4 * i + 1], lat[4 * i + 2], lat[4 * i + 3]);
}

// ---------------------------------------------------------------------------
// Kernel 3: discriminator (R5 logic). CHANGED vs R7: __launch_bounds__(256, 3)
// to cap regs at ~85 and lift occupancy 24.4% -> 37.5%.
// ---------------------------------------------------------------------------
__global__ void __launch_bounds__(256, 3)
disc_kernel(const float* __restrict__ W0, const float* __restrict__ b0,
            const float* __restrict__ W1, const float* __restrict__ b1,
            const float* __restrict__ W2, const float* __restrict__ b2,
            const float* __restrict__ W3, const float* __restrict__ b3,
            const float* __restrict__ W4, const float* __restrict__ b4,
            const float* __restrict__ dow, const float* __restrict__ dob,
            float* out, int BS)
{
    __shared__ __align__(16) float sW1[1536], sW4[1536];   // [48][32], [96][16]
    __shared__ __align__(16) float sW2[384],  sW3[384];    // [24][16], [48][8]
    __shared__ __align__(16) float sW0[96], sB0[96], sB4[96];
    __shared__ __align__(16) float sB1[48], sB3[48], sB2[24], sDow[32];
    __shared__ float sRec[16];
    __shared__ float sDob;

    const int NT = 256;
    int tid = threadIdx.x;

    for (int i = tid; i < 1536; i += NT) {
        { int j = i >> 5, k = i & 31; int t = j >> 4;
          int row = j + ((t > 0) ? 16 : 0);
          float sc = (t == 1) ? 1.0f : 0.5f;
          sW1[i] = sc * W1[row * 32 + k]; }
        { int j = i >> 4, k = i & 15; int t = j >> 5;
          int row = j + ((t > 0) ? 32 : 0);
          float sc = (t == 1) ? 1.0f : 0.5f;
          sW4[i] = sc * W4[row * 16 + k]; }
    }
    for (int i = tid; i < 384; i += NT) {
        { int j = i >> 4, k = i & 15; int t = j >> 3;
          int row = j + ((t > 0) ? 8 : 0);
          float sc = (t == 1) ? 1.0f : 0.5f;
          sW2[i] = sc * W2[row * 16 + k]; }
        { int j = i >> 3, k = i & 7; int t = j >> 4;
          int row = j + ((t > 0) ? 16 : 0);
          float sc = (t == 1) ? 1.0f : 0.5f;
          sW3[i] = sc * W3[row * 8 + k]; }
    }
    for (int i = tid; i < 96; i += NT) {
        int t = i >> 5; int row = i + ((t > 0) ? 32 : 0);
        float sc = (t == 1) ? 1.0f : 0.5f;
        sW0[i] = sc * W0[row];
        sB0[i] = sc * b0[row];
        sB4[i] = sc * b4[row];
    }
    if (tid < 48) {
        int t = tid >> 4; int row = tid + ((t > 0) ? 16 : 0);
        float sc = (t == 1) ? 1.0f : 0.5f;
        sB1[tid] = sc * b1[row];
        sB3[tid] = sc * b3[row];
    }
    if (tid < 24) {
        int t = tid >> 3; int row = tid + ((t > 0) ? 8 : 0);
        float sc = (t == 1) ? 1.0f : 0.5f;
        sB2[tid] = sc * b2[row];
    }
    if (tid < 32) sDow[tid] = dow[tid];
    if (tid < 16) sRec[tid] = g_dec_recon[tid];
    if (tid == 0) sDob = dob[0];
    __syncthreads();

    int idx = blockIdx.x * NT + tid;
    if (idx >= BS) return;

    float a = out[idx];   // imputed

#define UNIT(hi, gg, ho, dst)                                     \
    {                                                             \
        float si = fmaf(0.5f, tanh_a(hi), 0.5f);                  \
        float so = fmaf(0.5f, tanh_a(ho), 0.5f);                  \
        float cc = si * tanh_a(gg);                               \
        dst = so * tanh_a(cc);                                    \
    }

    float v0[32];
#pragma unroll
    for (int j = 0; j < 32; j++) {
        float hi = fmaf(a, sW0[j],      sB0[j]);
        float gg = fmaf(a, sW0[32 + j], sB0[32 + j]);
        float ho = fmaf(a, sW0[64 + j], sB0[64 + j]);
        UNIT(hi, gg, ho, v0[j]);
    }
    float v1[16];
#pragma unroll
    for (int j = 0; j < 16; j++) {
        float hi = dotN_acc<32>(sW1 + j * 32,        v0, sB1[j]);
        float gg = dotN_acc<32>(sW1 + (16 + j) * 32, v0, sB1[16 + j]);
        float ho = dotN_acc<32>(sW1 + (32 + j) * 32, v0, sB1[32 + j]);
        UNIT(hi, gg, ho, v1[j]);
    }
    float v2[8];
#pragma unroll
    for (int j = 0; j < 8; j++) {
        float hi = dotN_acc<16>(sW2 + j * 16,        v1, sB2[j]);
        float gg = dotN_acc<16>(sW2 + (8 + j) * 16,  v1, sB2[8 + j]);
        float ho = dotN_acc<16>(sW2 + (16 + j) * 16, v1, sB2[16 + j]);
        UNIT(hi, gg, ho, v2[j]);
    }
    float v3[16];
#pragma unroll
    for (int j = 0; j < 16; j++) {
        float hi = dotN_acc<8>(sW3 + j * 8,        v2, sB3[j]);
        float gg = dotN_acc<8>(sW3 + (16 + j) * 8, v2, sB3[16 + j]);
        float ho = dotN_acc<8>(sW3 + (32 + j) * 8, v2, sB3[32 + j]);
        UNIT(hi, gg, ho, v3[j]);
    }
    float r = sDob;
#pragma unroll
    for (int j = 0; j < 32; j++) {
        float hi = dotN_acc<16>(sW4 + j * 16,        v3, sB4[j]);
        float gg = dotN_acc<16>(sW4 + (32 + j) * 16, v3, sB4[32 + j]);
        float ho = dotN_acc<16>(sW4 + (64 + j) * 16, v3, sB4[64 + j]);
        float v4;
        UNIT(hi, gg, ho, v4);
        r = fmaf(v4, sDow[j], r);
    }
#undef UNIT

    out[(size_t)BS + idx] = r;
    out[3 * (size_t)BS + idx] = sRec[idx & 15];
}

// ---------------------------------------------------------------------------
extern "C" void kernel_launch(void* const* d_in, const int* in_sizes, int n_in,
                              void* d_out, int out_size)
{
    const float* values = (const float*)d_in[0];
    const int*   masks  = (const int*)  d_in[1];
    const float* gfW = (const float*)d_in[2];
    const float* gfU = (const float*)d_in[3];
    const float* gfb = (const float*)d_in[4];
    const float* gbW = (const float*)d_in[5];
    const float* gbU = (const float*)d_in[6];
    const float* gbb = (const float*)d_in[7];
    const float* impW = (const float*)d_in[8];
    const float* impB = (const float*)d_in[9];
    const float* fcW  = (const float*)d_in[10];
    const float* fcB  = (const float*)d_in[11];
    const float* dWih = (const float*)d_in[12];
    const float* dWhh = (const float*)d_in[13];
    const float* db_  = (const float*)d_in[14];
    const float* dOW  = (const float*)d_in[15];
    const float* dOB  = (const float*)d_in[16];
    const float* dow  = (const float*)d_in[17];
    const float* dob  = (const float*)d_in[18];
    const float* W0 = (const float*)d_in[19]; const float* b0 = (const float*)d_in[20];
    const float* W1 = (const float*)d_in[21]; const float* b1 = (const float*)d_in[22];
    const float* W2 = (const float*)d_in[23]; const float* b2 = (const float*)d_in[24];
    const float* W3 = (const float*)d_in[25]; const float* b3 = (const float*)d_in[26];
    const float* W4 = (const float*)d_in[27]; const float* b4 = (const float*)d_in[28];

    float* out = (float*)d_out;
    int B  = in_sizes[0] / 16;     // 32768
    int BS = B * 16;               // 524288

    setup_kernel<<<1, 64>>>(gfW, gfb, gbW, gbb, dWih, dWhh, db_, dOW, dOB);
    gen_kernel<<<(B + 127) / 128, 128>>>(values, masks, gfU, gfW, gfb,
                                         gbU, gbW, gbb, impW, impB, fcW, fcB, out, B);
    disc_kernel<<<(BS + 255) / 256, 256>>>(W0, b0, W1, b1, W2, b2, W3, b3, W4, b4,
                                           dow, dob, out, BS);
}

// round 9
// speedup vs baseline: 4.4919x; 1.0973x over previous
#include <cuda_runtime.h>
#include <cuda_bf16.h>
#include <cstdint>

// out layout (fp32): [0,BS) imputed | [BS,2BS) disc | [2BS,3BS) latent | [3BS,4BS) recon
// BS = B*16

#define S16 16
#define H16 16

__device__ float g_dec_recon[16];  // reconstructed[s] (batch-independent)

// ---- activations ----------------------------------------------------------
__device__ __forceinline__ float fast_ex2(float x) {
    float y; asm("ex2.approx.f32 %0, %1;" : "=f"(y) : "f"(x)); return y;
}
__device__ __forceinline__ float fast_rcp(float x) {
    float y; asm("rcp.approx.f32 %0, %1;" : "=f"(y) : "f"(x)); return y;
}
__device__ __forceinline__ float sigmoidf_(float x) {
    return fast_rcp(1.0f + fast_ex2(-1.4426950408889634f * x));
}
__device__ __forceinline__ float tanhf_(float x) {
    float t = fast_ex2(-2.8853901f * x);
    return fmaf(2.0f, fast_rcp(1.0f + t), -1.0f);
}
// fast (feedforward disc only; proven rel_err ~2.7e-6)
__device__ __forceinline__ float tanh_a(float x) {
    float y; asm("tanh.approx.f32 %0, %1;" : "=f"(y) : "f"(x)); return y;
}

// dot over N (multiple of 4) smem weights (16B-aligned rows) x register vector
template <int N>
__device__ __forceinline__ float dotN_acc(const float* __restrict__ w,
                                          const float* __restrict__ v, float acc) {
#pragma unroll
    for (int k = 0; k < N; k += 4) {
        float4 wv = *reinterpret_cast<const float4*>(w + k);
        acc = fmaf(v[k + 0], wv.x, acc);
        acc = fmaf(v[k + 1], wv.y, acc);
        acc = fmaf(v[k + 2], wv.z, acc);
        acc = fmaf(v[k + 3], wv.w, acc);
    }
    return acc;
}

// one LSTM cell step, H=16, scalar input cc. h,c live in registers.
__device__ __forceinline__ void lstm_step16(float h[16], float c[16], float cc,
                                            const float* __restrict__ U,     // [64][16] smem
                                            const float* __restrict__ wih,   // [64] smem
                                            const float* __restrict__ bias)  // [64] smem
{
    float hn[16];
#pragma unroll
    for (int j = 0; j < 16; j++) {
        float gi = dotN_acc<16>(U + (j +  0) * 16, h, fmaf(cc, wih[j +  0], bias[j +  0]));
        float gf = dotN_acc<16>(U + (j + 16) * 16, h, fmaf(cc, wih[j + 16], bias[j + 16]));
        float gg = dotN_acc<16>(U + (j + 32) * 16, h, fmaf(cc, wih[j + 32], bias[j + 32]));
        float go = dotN_acc<16>(U + (j + 48) * 16, h, fmaf(cc, wih[j + 48], bias[j + 48]));
        float cn = fmaf(sigmoidf_(gf), c[j], sigmoidf_(gi) * tanhf_(gg));
        c[j] = cn;
        hn[j] = sigmoidf_(go) * tanhf_(cn);
    }
#pragma unroll
    for (int j = 0; j < 16; j++) h[j] = hn[j];
}

// ---------------------------------------------------------------------------
// Generator. One thread per batch row (R1 structure). CHANGED vs R8:
//  - sInit computed block-locally by 16 threads (no setup kernel needed)
//  - last block runs the batch-independent decoder recurrence concurrently
//    (R3/R5-proven pattern), writing g_dec_recon for disc_kernel.
// ---------------------------------------------------------------------------
__global__ void __launch_bounds__(128)
gen_kernel(const float* __restrict__ values, const int* __restrict__ masks,
           const float* __restrict__ gfU, const float* __restrict__ gfW, const float* __restrict__ gfb,
           const float* __restrict__ gbU, const float* __restrict__ gbW, const float* __restrict__ gbb,
           const float* __restrict__ impW, const float* __restrict__ impB,
           const float* __restrict__ fcW, const float* __restrict__ fcB,
           const float* __restrict__ dWih, const float* __restrict__ dWhh,
           const float* __restrict__ db_, const float* __restrict__ dOW, const float* __restrict__ dOB,
           float* __restrict__ out, int B)
{
    __shared__ __align__(16) float sUf[1024], sUb[1024];
    __shared__ __align__(16) float sWf[64], sWb[64], sBf[64], sBb[64];
    __shared__ __align__(16) float sImpW[16], sFcW[256], sFcB[16], sInit[64];

    const int NT = 128;
    int tid = threadIdx.x;

    // ---- last block: batch-independent decoder recurrence (R8 setup logic) ----
    if (blockIdx.x == gridDim.x - 1) {
        float* sWih = sUf;    // 1024 floats
        float* sWhh = sUb;    // 1024 floats
        float* sb   = sWf;    // 64  (sWf+sWb contiguous enough? use separate named arrays)
        float* sOW  = sImpW;  // 16
        float* shd  = sInit;        // 16
        float* scd  = sInit + 16;   // 16
        float* sgat = sBf;          // 64

        for (int i = tid; i < 1024; i += NT) { sWih[i] = dWih[i]; sWhh[i] = dWhh[i]; }
        if (tid < 64) sb[tid] = db_[tid];
        if (tid < 16) sOW[tid] = dOW[tid];
        __syncthreads();

        if (tid < 16) {
            float si = sb[tid], sg = sb[tid + 32], so = sb[tid + 48];
#pragma unroll
            for (int k = 0; k < 16; k++) {
                si = fmaf(128.0f, sWih[(tid +  0) * 16 + k], si);
                sg = fmaf(128.0f, sWih[(tid + 32) * 16 + k], sg);
                so = fmaf(128.0f, sWih[(tid + 48) * 16 + k], so);
            }
            float c = sigmoidf_(si) * tanhf_(sg);
            float h = sigmoidf_(so) * tanhf_(c);
            shd[tid] = h; scd[tid] = c;
        }
        __syncthreads();

        for (int s = 0; s < S16; s++) {
            if (tid < 64) {
                float acc = sb[tid];
#pragma unroll
                for (int k = 0; k < 16; k++)
                    acc = fmaf(scd[k], sWih[tid * 16 + k], fmaf(shd[k], sWhh[tid * 16 + k], acc));
                sgat[tid] = acc;
            }
            __syncthreads();
            if (tid < 16) {
                float c = fmaf(sigmoidf_(sgat[tid + 16]), scd[tid],
                               sigmoidf_(sgat[tid]) * tanhf_(sgat[tid + 32]));
                float h = sigmoidf_(sgat[tid + 48]) * tanhf_(c);
                scd[tid] = c; shd[tid] = h;
            }
            __syncthreads();
            if (tid == 0) {
                float acc = dOB[0];
#pragma unroll
                for (int k = 0; k < 16; k++) acc = fmaf(shd[k], sOW[k], acc);
                g_dec_recon[s] = acc;
            }
            __syncthreads();
        }
        return;
    }

    // ---- stage weights ----
    for (int i = tid; i < 1024; i += NT) { sUf[i] = gfU[i]; sUb[i] = gbU[i]; }
    for (int i = tid; i < 64; i += NT) {
        sWf[i] = gfW[i]; sWb[i] = gbW[i]; sBf[i] = gfb[i]; sBb[i] = gbb[i];
    }
    for (int i = tid; i < 256; i += NT) sFcW[i] = fcW[i];
    if (tid < 16) { sImpW[tid] = impW[tid]; sFcB[tid] = fcB[tid]; }
    __syncthreads();

    // ---- block-local init (x = +-128, h = c = 0), 16 threads -> sInit ----
    if (tid < 16) {
        {
            float gi = fmaf(128.0f, sWf[tid],      sBf[tid]);
            float gg = fmaf(128.0f, sWf[tid + 32], sBf[tid + 32]);
            float go = fmaf(128.0f, sWf[tid + 48], sBf[tid + 48]);
            float c = sigmoidf_(gi) * tanhf_(gg);
            sInit[16 + tid] = c;
            sInit[tid] = sigmoidf_(go) * tanhf_(c);
        }
        {
            float gi = fmaf(-128.0f, sWb[tid],      sBb[tid]);
            float gg = fmaf(-128.0f, sWb[tid + 32], sBb[tid + 32]);
            float go = fmaf(-128.0f, sWb[tid + 48], sBb[tid + 48]);
            float c = sigmoidf_(gi) * tanhf_(gg);
            sInit[48 + tid] = c;
            sInit[32 + tid] = sigmoidf_(go) * tanhf_(c);
        }
    }
    __syncthreads();

    int b = blockIdx.x * NT + tid;
    if (b >= B) return;
    float impb = __ldg(impB);

    const float* vrow = values + (size_t)b * S16;
    const int*   mrow = masks  + (size_t)b * S16;

    float hf[16], cf[16], hb[16], cb[16];
#pragma unroll
    for (int k = 0; k < 16; k++) {
        hf[k] = sInit[k]; cf[k] = sInit[16 + k];
        hb[k] = sInit[32 + k]; cb[k] = sInit[48 + k];
    }

#pragma unroll 1
    for (int t = 0; t < S16; t++) {
        float xt = __ldg(vrow + t);
        float mt = (float)__ldg(mrow + t);
        float df = dotN_acc<16>(sImpW, hf, impb);
        float db = dotN_acc<16>(sImpW, hb, impb);
        float ccf = fmaf(mt, df - xt, xt);
        float ccb = fmaf(mt, db - xt, xt);
        lstm_step16(hf, cf, ccf, sUf, sWf, sBf);
        lstm_step16(hb, cb, ccb, sUb, sWb, sBb);
    }

    float h[16];
#pragma unroll
    for (int k = 0; k < 16; k++) h[k] = hf[k] + hb[k];

    size_t BS = (size_t)B * S16;

    float impv[16];
#pragma unroll
    for (int s = 0; s < 16; s++) {
        float xt = __ldg(vrow + s);
        float mt = (float)__ldg(mrow + s);
        impv[s] = fmaf(mt, xt - h[s], h[s]);
    }
    float4* o4 = reinterpret_cast<float4*>(out + (size_t)b * 16);
#pragma unroll
    for (int i = 0; i < 4; i++)
        o4[i] = make_float4(impv[4 * i], impv[4 * i + 1], impv[4 * i + 2], impv[4 * i + 3]);

    float lat[16];
#pragma unroll
    for (int l = 0; l < 16; l++) lat[l] = dotN_acc<16>(sFcW + l * 16, h, sFcB[l]);
    float4* l4 = reinterpret_cast<float4*>(out + 2 * BS + (size_t)b * 16);
#pragma unroll
    for (int i = 0; i < 4; i++)
        l4[i] = make_float4(lat[4 * i], lat[4 * i + 1], lat[4 * i + 2], lat[4 * i + 3]);
}

// ---------------------------------------------------------------------------
// Discriminator (VERBATIM R8): one sample per thread; 'f' gate dead;
// i/o weights pre-halved so sigmoid = 0.5*tanh(x/2)+0.5.
// ---------------------------------------------------------------------------
__global__ void __launch_bounds__(256, 3)
disc_kernel(const float* __restrict__ W0, const float* __restrict__ b0,
            const float* __restrict__ W1, const float* __restrict__ b1,
            const float* __restrict__ W2, const float* __restrict__ b2,
            const float* __restrict__ W3, const float* __restrict__ b3,
            const float* __restrict__ W4, const float* __restrict__ b4,
            const float* __restrict__ dow, const float* __restrict__ dob,
            float* out, int BS)
{
    __shared__ __align__(16) float sW1[1536], sW4[1536];   // [48][32], [96][16]
    __shared__ __align__(16) float sW2[384],  sW3[384];    // [24][16], [48][8]
    __shared__ __align__(16) float sW0[96], sB0[96], sB4[96];
    __shared__ __align__(16) float sB1[48], sB3[48], sB2[24], sDow[32];
    __shared__ float sRec[16];
    __shared__ float sDob;

    const int NT = 256;
    int tid = threadIdx.x;

    for (int i = tid; i < 1536; i += NT) {
        { int j = i >> 5, k = i & 31; int t = j >> 4;
          int row = j + ((t > 0) ? 16 : 0);
          float sc = (t == 1) ? 1.0f : 0.5f;
          sW1[i] = sc * W1[row * 32 + k]; }
        { int j = i >> 4, k = i & 15; int t = j >> 5;
          int row = j + ((t > 0) ? 32 : 0);
          float sc = (t == 1) ? 1.0f : 0.5f;
          sW4[i] = sc * W4[row * 16 + k]; }
    }
    for (int i = tid; i < 384; i += NT) {
        { int j = i >> 4, k = i & 15; int t = j >> 3;
          int row = j + ((t > 0) ? 8 : 0);
          float sc = (t == 1) ? 1.0f : 0.5f;
          sW2[i] = sc * W2[row * 16 + k]; }
        { int j = i >> 3, k = i & 7; int t = j >> 4;
          int row = j + ((t > 0) ? 16 : 0);
          float sc = (t == 1) ? 1.0f : 0.5f;
          sW3[i] = sc * W3[row * 8 + k]; }
    }
    for (int i = tid; i < 96; i += NT) {
        int t = i >> 5; int row = i + ((t > 0) ? 32 : 0);
        float sc = (t == 1) ? 1.0f : 0.5f;
        sW0[i] = sc * W0[row];
        sB0[i] = sc * b0[row];
        sB4[i] = sc * b4[row];
    }
    if (tid < 48) {
        int t = tid >> 4; int row = tid + ((t > 0) ? 16 : 0);
        float sc = (t == 1) ? 1.0f : 0.5f;
        sB1[tid] = sc * b1[row];
        sB3[tid] = sc * b3[row];
    }
    if (tid < 24) {
        int t = tid >> 3; int row = tid + ((t > 0) ? 8 : 0);
        float sc = (t == 1) ? 1.0f : 0.5f;
        sB2[tid] = sc * b2[row];
    }
    if (tid < 32) sDow[tid] = dow[tid];
    if (tid < 16) sRec[tid] = g_dec_recon[tid];
    if (tid == 0) sDob = dob[0];
    __syncthreads();

    int idx = blockIdx.x * NT + tid;
    if (idx >= BS) return;

    float a = out[idx];   // imputed

#define UNIT(hi, gg, ho, dst)                                     \
    {                                                             \
        float si = fmaf(0.5f, tanh_a(hi), 0.5f);                  \
        float so = fmaf(0.5f, tanh_a(ho), 0.5f);                  \
        float cc = si * tanh_a(gg);                               \
        dst = so * tanh_a(cc);                                    \
    }

    float v0[32];
#pragma unroll
    for (int j = 0; j < 32; j++) {
        float hi = fmaf(a, sW0[j],      sB0[j]);
        float gg = fmaf(a, sW0[32 + j], sB0[32 + j]);
        float ho = fmaf(a, sW0[64 + j], sB0[64 + j]);
        UNIT(hi, gg, ho, v0[j]);
    }
    float v1[16];
#pragma unroll
    for (int j = 0; j < 16; j++) {
        float hi = dotN_acc<32>(sW1 + j * 32,        v0, sB1[j]);
        float gg = dotN_acc<32>(sW1 + (16 + j) * 32, v0, sB1[16 + j]);
        float ho = dotN_acc<32>(sW1 + (32 + j) * 32, v0, sB1[32 + j]);
        UNIT(hi, gg, ho, v1[j]);
    }
    float v2[8];
#pragma unroll
    for (int j = 0; j < 8; j++) {
        float hi = dotN_acc<16>(sW2 + j * 16,        v1, sB2[j]);
        float gg = dotN_acc<16>(sW2 + (8 + j) * 16,  v1, sB2[8 + j]);
        float ho = dotN_acc<16>(sW2 + (16 + j) * 16, v1, sB2[16 + j]);
        UNIT(hi, gg, ho, v2[j]);
    }
    float v3[16];
#pragma unroll
    for (int j = 0; j < 16; j++) {
        float hi = dotN_acc<8>(sW3 + j * 8,        v2, sB3[j]);
        float gg = dotN_acc<8>(sW3 + (16 + j) * 8, v2, sB3[16 + j]);
        float ho = dotN_acc<8>(sW3 + (32 + j) * 8, v2, sB3[32 + j]);
        UNIT(hi, gg, ho, v3[j]);
    }
    float r = sDob;
#pragma unroll
    for (int j = 0; j < 32; j++) {
        float hi = dotN_acc<16>(sW4 + j * 16,        v3, sB4[j]);
        float gg = dotN_acc<16>(sW4 + (32 + j) * 16, v3, sB4[32 + j]);
        float ho = dotN_acc<16>(sW4 + (64 + j) * 16, v3, sB4[64 + j]);
        float v4;
        UNIT(hi, gg, ho, v4);
        r = fmaf(v4, sDow[j], r);
    }
#undef UNIT

    out[(size_t)BS + idx] = r;
    out[3 * (size_t)BS + idx] = sRec[idx & 15];
}

// ---------------------------------------------------------------------------
extern "C" void kernel_launch(void* const* d_in, const int* in_sizes, int n_in,
                              void* d_out, int out_size)
{
    const float* values = (const float*)d_in[0];
    const int*   masks  = (const int*)  d_in[1];
    const float* gfW = (const float*)d_in[2];
    const float* gfU = (const float*)d_in[3];
    const float* gfb = (const float*)d_in[4];
    const float* gbW = (const float*)d_in[5];
    const float* gbU = (const float*)d_in[6];
    const float* gbb = (const float*)d_in[7];
    const float* impW = (const float*)d_in[8];
    const float* impB = (const float*)d_in[9];
    const float* fcW  = (const float*)d_in[10];
    const float* fcB  = (const float*)d_in[11];
    const float* dWih = (const float*)d_in[12];
    const float* dWhh = (const float*)d_in[13];
    const float* db_  = (const float*)d_in[14];
    const float* dOW  = (const float*)d_in[15];
    const float* dOB  = (const float*)d_in[16];
    const float* dow  = (const float*)d_in[17];
    const float* dob  = (const float*)d_in[18];
    const float* W0 = (const float*)d_in[19]; const float* b0 = (const float*)d_in[20];
    const float* W1 = (const float*)d_in[21]; const float* b1 = (const float*)d_in[22];
    const float* W2 = (const float*)d_in[23]; const float* b2 = (const float*)d_in[24];
    const float* W3 = (const float*)d_in[25]; const float* b3 = (const float*)d_in[26];
    const float* W4 = (const float*)d_in[27]; const float* b4 = (const float*)d_in[28];

    float* out = (float*)d_out;
    int B  = in_sizes[0] / 16;     // 32768
    int BS = B * 16;               // 524288

    gen_kernel<<<(B + 127) / 128 + 1, 128>>>(values, masks, gfU, gfW, gfb,
                                             gbU, gbW, gbb, impW, impB, fcW, fcB,
                                             dWih, dWhh, db_, dOW, dOB, out, B);
    disc_kernel<<<(BS + 255) / 256, 256>>>(W0, b0, W1, b1, W2, b2, W3, b3, W4, b4,
                                           dow, dob, out, BS);
}

// round 10
// speedup vs baseline: 4.5899x; 1.0218x over previous
#include <cuda_runtime.h>
#include <cuda_bf16.h>
#include <cstdint>

// out layout (fp32): [0,BS) imputed | [BS,2BS) disc | [2BS,3BS) latent | [3BS,4BS) recon
// BS = B*16

#define S16 16

__device__ float g_dec_recon[16];        // batch-independent decoder output
__device__ float g_h[2][32768 * 16];     // per-direction final hidden states

// ---- activations ----------------------------------------------------------
__device__ __forceinline__ float fast_ex2(float x) {
    float y; asm("ex2.approx.f32 %0, %1;" : "=f"(y) : "f"(x)); return y;
}
__device__ __forceinline__ float fast_rcp(float x) {
    float y; asm("rcp.approx.f32 %0, %1;" : "=f"(y) : "f"(x)); return y;
}
__device__ __forceinline__ float sigmoidf_(float x) {
    return fast_rcp(1.0f + fast_ex2(-1.4426950408889634f * x));
}
__device__ __forceinline__ float tanhf_(float x) {
    float t = fast_ex2(-2.8853901f * x);
    return fmaf(2.0f, fast_rcp(1.0f + t), -1.0f);
}
// fast (feedforward disc only; proven rel_err ~2.7e-6)
__device__ __forceinline__ float tanh_a(float x) {
    float y; asm("tanh.approx.f32 %0, %1;" : "=f"(y) : "f"(x)); return y;
}

// dot over N (multiple of 4) smem weights (16B-aligned rows) x register vector
template <int N>
__device__ __forceinline__ float dotN_acc(const float* __restrict__ w,
                                          const float* __restrict__ v, float acc) {
#pragma unroll
    for (int k = 0; k < N; k += 4) {
        float4 wv = *reinterpret_cast<const float4*>(w + k);
        acc = fmaf(v[k + 0], wv.x, acc);
        acc = fmaf(v[k + 1], wv.y, acc);
        acc = fmaf(v[k + 2], wv.z, acc);
        acc = fmaf(v[k + 3], wv.w, acc);
    }
    return acc;
}

// one LSTM cell step, H=16, scalar input cc. h,c live in registers.
// COMPILE-TIME-FIXED smem arrays only (per-lane runtime bases are a known
// 20x codegen pathology on this toolchain).
__device__ __forceinline__ void lstm_step16(float h[16], float c[16], float cc,
                                            const float* __restrict__ U,     // [64][16] smem
                                            const float* __restrict__ wih,   // [64] smem
                                            const float* __restrict__ bias)  // [64] smem
{
    float hn[16];
#pragma unroll
    for (int j = 0; j < 16; j++) {
        float gi = dotN_acc<16>(U + (j +  0) * 16, h, fmaf(cc, wih[j +  0], bias[j +  0]));
        float gf = dotN_acc<16>(U + (j + 16) * 16, h, fmaf(cc, wih[j + 16], bias[j + 16]));
        float gg = dotN_acc<16>(U + (j + 32) * 16, h, fmaf(cc, wih[j + 32], bias[j + 32]));
        float go = dotN_acc<16>(U + (j + 48) * 16, h, fmaf(cc, wih[j + 48], bias[j + 48]));
        float cn = fmaf(sigmoidf_(gf), c[j], sigmoidf_(gi) * tanhf_(gg));
        c[j] = cn;
        hn[j] = sigmoidf_(go) * tanhf_(cn);
    }
#pragma unroll
    for (int j = 0; j < 16; j++) h[j] = hn[j];
}

// ---------------------------------------------------------------------------
// Generator: direction split at BLOCK granularity (block-uniform global
// pointer selection at staging time; hot loop on fixed smem arrays).
// Blocks [0,NB): fwd. [NB,2NB): bwd. Last block: decoder recurrence.
// Each thread runs ONE 16-step LSTM and stores its final h to g_h[dir].
// ---------------------------------------------------------------------------
__global__ void __launch_bounds__(128)
gen_kernel(const float* __restrict__ values, const int* __restrict__ masks,
           const float* __restrict__ gfU, const float* __restrict__ gfW, const float* __restrict__ gfb,
           const float* __restrict__ gbU, const float* __restrict__ gbW, const float* __restrict__ gbb,
           const float* __restrict__ impW, const float* __restrict__ impB,
           const float* __restrict__ dWih, const float* __restrict__ dWhh,
           const float* __restrict__ db_, const float* __restrict__ dOW, const float* __restrict__ dOB,
           int B)
{
    __shared__ __align__(16) float sU[1024];
    __shared__ __align__(16) float sW[64], sB[64];
    __shared__ __align__(16) float sImpW[16], sInit[32];
    __shared__ __align__(16) float sAux[1024];   // decoder Whh / spare

    const int NT = 128;
    int tid = threadIdx.x;

    // ---- last block: batch-independent decoder recurrence ----
    if (blockIdx.x == gridDim.x - 1) {
        float* sWih = sU;          // 1024
        float* sWhh = sAux;        // 1024
        float* sb   = sW;          // 64
        float* sOW  = sImpW;       // 16
        float* shd  = sInit;       // 16
        float* scd  = sInit + 16;  // 16
        float* sgat = sB;          // 64

        for (int i = tid; i < 1024; i += NT) { sWih[i] = dWih[i]; sWhh[i] = dWhh[i]; }
        if (tid < 64) sb[tid] = db_[tid];
        if (tid < 16) sOW[tid] = dOW[tid];
        __syncthreads();

        if (tid < 16) {
            float si = sb[tid], sg = sb[tid + 32], so = sb[tid + 48];
#pragma unroll
            for (int k = 0; k < 16; k++) {
                si = fmaf(128.0f, sWih[(tid +  0) * 16 + k], si);
                sg = fmaf(128.0f, sWih[(tid + 32) * 16 + k], sg);
                so = fmaf(128.0f, sWih[(tid + 48) * 16 + k], so);
            }
            float c = sigmoidf_(si) * tanhf_(sg);
            float h = sigmoidf_(so) * tanhf_(c);
            shd[tid] = h; scd[tid] = c;
        }
        __syncthreads();

        for (int s = 0; s < S16; s++) {
            if (tid < 64) {
                float acc = sb[tid];
#pragma unroll
                for (int k = 0; k < 16; k++)
                    acc = fmaf(scd[k], sWih[tid * 16 + k], fmaf(shd[k], sWhh[tid * 16 + k], acc));
                sgat[tid] = acc;
            }
            __syncthreads();
            if (tid < 16) {
                float c = fmaf(sigmoidf_(sgat[tid + 16]), scd[tid],
                               sigmoidf_(sgat[tid]) * tanhf_(sgat[tid + 32]));
                float h = sigmoidf_(sgat[tid + 48]) * tanhf_(c);
                scd[tid] = c; shd[tid] = h;
            }
            __syncthreads();
            if (tid == 0) {
                float acc = dOB[0];
#pragma unroll
                for (int k = 0; k < 16; k++) acc = fmaf(shd[k], sOW[k], acc);
                g_dec_recon[s] = acc;
            }
            __syncthreads();
        }
        return;
    }

    // ---- direction for this whole block (uniform) ----
    int nb = (gridDim.x - 1) >> 1;
    int dirb = (blockIdx.x >= nb) ? 1 : 0;
    const float* Ug = dirb ? gbU : gfU;
    const float* Wg = dirb ? gbW : gfW;
    const float* Bg = dirb ? gbb : gfb;
    float x0 = dirb ? -128.0f : 128.0f;

    for (int i = tid; i < 1024; i += NT) sU[i] = Ug[i];
    for (int i = tid; i < 64; i += NT) { sW[i] = Wg[i]; sB[i] = Bg[i]; }
    if (tid < 16) sImpW[tid] = impW[tid];
    __syncthreads();

    // ---- block-local init (x = x0, h = c = 0), 16 threads -> sInit ----
    if (tid < 16) {
        float gi = fmaf(x0, sW[tid],      sB[tid]);
        float gg = fmaf(x0, sW[tid + 32], sB[tid + 32]);
        float go = fmaf(x0, sW[tid + 48], sB[tid + 48]);
        float c = sigmoidf_(gi) * tanhf_(gg);
        sInit[16 + tid] = c;
        sInit[tid] = sigmoidf_(go) * tanhf_(c);
    }
    __syncthreads();

    int b = (blockIdx.x - (dirb ? nb : 0)) * NT + tid;
    if (b >= B) return;
    float impb = __ldg(impB);

    const float* vrow = values + (size_t)b * S16;
    const int*   mrow = masks  + (size_t)b * S16;

    float h[16], c[16];
#pragma unroll
    for (int k = 0; k < 16; k++) { h[k] = sInit[k]; c[k] = sInit[16 + k]; }

#pragma unroll 1
    for (int t = 0; t < S16; t++) {
        float xt = __ldg(vrow + t);
        float mt = (float)__ldg(mrow + t);
        float d = dotN_acc<16>(sImpW, h, impb);
        float cc = fmaf(mt, d - xt, xt);
        lstm_step16(h, c, cc, sU, sW, sB);
    }

    // store final h for this direction
    float* dst = &g_h[dirb][(size_t)b * 16];
    float4* d4 = reinterpret_cast<float4*>(dst);
#pragma unroll
    for (int i = 0; i < 4; i++)
        d4[i] = make_float4(h[4 * i], h[4 * i + 1], h[4 * i + 2], h[4 * i + 3]);
}

// ---------------------------------------------------------------------------
// Discriminator + combine epilogue. Thread (b,s): recombine hs = hf+hb,
// compute imputed (bit-identical fma), latent row s, then the disc net.
// Disc net logic verbatim R8: 'f' gate dead; i/o weights pre-halved.
// ---------------------------------------------------------------------------
__global__ void __launch_bounds__(256, 3)
disc_kernel(const float* __restrict__ values, const int* __restrict__ masks,
            const float* __restrict__ fcW, const float* __restrict__ fcB,
            const float* __restrict__ W0, const float* __restrict__ b0,
            const float* __restrict__ W1, const float* __restrict__ b1,
            const float* __restrict__ W2, const float* __restrict__ b2,
            const float* __restrict__ W3, const float* __restrict__ b3,
            const float* __restrict__ W4, const float* __restrict__ b4,
            const float* __restrict__ dow, const float* __restrict__ dob,
            float* out, int BS)
{
    __shared__ __align__(16) float sW1[1536], sW4[1536];   // [48][32], [96][16]
    __shared__ __align__(16) float sW2[384],  sW3[384];    // [24][16], [48][8]
    __shared__ __align__(16) float sW0[96], sB0[96], sB4[96];
    __shared__ __align__(16) float sB1[48], sB3[48], sB2[24], sDow[32];
    __shared__ __align__(16) float sFcWT[256], sFcB[16];   // fcW transposed [k][l]
    __shared__ float sRec[16];
    __shared__ float sDob;

    const int NT = 256;
    int tid = threadIdx.x;

    for (int i = tid; i < 1536; i += NT) {
        { int j = i >> 5, k = i & 31; int t = j >> 4;
          int row = j + ((t > 0) ? 16 : 0);
          float sc = (t == 1) ? 1.0f : 0.5f;
          sW1[i] = sc * W1[row * 32 + k]; }
        { int j = i >> 4, k = i & 15; int t = j >> 5;
          int row = j + ((t > 0) ? 32 : 0);
          float sc = (t == 1) ? 1.0f : 0.5f;
          sW4[i] = sc * W4[row * 16 + k]; }
    }
    for (int i = tid; i < 384; i += NT) {
        { int j = i >> 4, k = i & 15; int t = j >> 3;
          int row = j + ((t > 0) ? 8 : 0);
          float sc = (t == 1) ? 1.0f : 0.5f;
          sW2[i] = sc * W2[row * 16 + k]; }
        { int j = i >> 3, k = i & 7; int t = j >> 4;
          int row = j + ((t > 0) ? 16 : 0);
          float sc = (t == 1) ? 1.0f : 0.5f;
          sW3[i] = sc * W3[row * 8 + k]; }
    }
    for (int i = tid; i < 96; i += NT) {
        int t = i >> 5; int row = i + ((t > 0) ? 32 : 0);
        float sc = (t == 1) ? 1.0f : 0.5f;
        sW0[i] = sc * W0[row];
        sB0[i] = sc * b0[row];
        sB4[i] = sc * b4[row];
    }
    for (int i = tid; i < 256; i += NT) {
        int k = i >> 4, l = i & 15;
        sFcWT[i] = fcW[l * 16 + k];      // transpose: [k][l]
    }
    if (tid < 48) {
        int t = tid >> 4; int row = tid + ((t > 0) ? 16 : 0);
        float sc = (t == 1) ? 1.0f : 0.5f;
        sB1[tid] = sc * b1[row];
        sB3[tid] = sc * b3[row];
    }
    if (tid < 24) {
        int t = tid >> 3; int row = tid + ((t > 0) ? 8 : 0);
        float sc = (t == 1) ? 1.0f : 0.5f;
        sB2[tid] = sc * b2[row];
    }
    if (tid < 32) sDow[tid] = dow[tid];
    if (tid < 16) { sRec[tid] = g_dec_recon[tid]; sFcB[tid] = fcB[tid]; }
    if (tid == 0) sDob = dob[0];
    __syncthreads();

    int idx = blockIdx.x * NT + tid;
    if (idx >= BS) return;

    int b = idx >> 4, s = idx & 15;

    // ---- combine epilogue: hs = hf + hb ----
    float hs[16];
    {
        const float4* hf4 = reinterpret_cast<const float4*>(&g_h[0][(size_t)b * 16]);
        const float4* hb4 = reinterpret_cast<const float4*>(&g_h[1][(size_t)b * 16]);
#pragma unroll
        for (int i = 0; i < 4; i++) {
            float4 f = __ldg(hf4 + i), g = __ldg(hb4 + i);
            hs[4 * i + 0] = f.x + g.x;
            hs[4 * i + 1] = f.y + g.y;
            hs[4 * i + 2] = f.z + g.z;
            hs[4 * i + 3] = f.w + g.w;
        }
    }

    float xt = __ldg(values + idx);
    float mt = (float)__ldg(masks + idx);
    float a = fmaf(mt, xt - hs[s], hs[s]);        // imputed (bit-identical)
    out[idx] = a;

    // latent row s = dot(fcW[s], hs) + fcB[s]
    {
        float lat = sFcB[s];
#pragma unroll
        for (int k = 0; k < 16; k++) lat = fmaf(hs[k], sFcWT[k * 16 + s], lat);
        out[2 * (size_t)BS + idx] = lat;
    }

#define UNIT(hi, gg, ho, dst)                                     \
    {                                                             \
        float si = fmaf(0.5f, tanh_a(hi), 0.5f);                  \
        float so = fmaf(0.5f, tanh_a(ho), 0.5f);                  \
        float cc = si * tanh_a(gg);                               \
        dst = so * tanh_a(cc);                                    \
    }

    float v0[32];
#pragma unroll
    for (int j = 0; j < 32; j++) {
        float hi = fmaf(a, sW0[j],      sB0[j]);
        float gg = fmaf(a, sW0[32 + j], sB0[32 + j]);
        float ho = fmaf(a, sW0[64 + j], sB0[64 + j]);
        UNIT(hi, gg, ho, v0[j]);
    }
    float v1[16];
#pragma unroll
    for (int j = 0; j < 16; j++) {
        float hi = dotN_acc<32>(sW1 + j * 32,        v0, sB1[j]);
        float gg = dotN_acc<32>(sW1 + (16 + j) * 32, v0, sB1[16 + j]);
        float ho = dotN_acc<32>(sW1 + (32 + j) * 32, v0, sB1[32 + j]);
        UNIT(hi, gg, ho, v1[j]);
    }
    float v2[8];
#pragma unroll
    for (int j = 0; j < 8; j++) {
        float hi = dotN_acc<16>(sW2 + j * 16,        v1, sB2[j]);
        float gg = dotN_acc<16>(sW2 + (8 + j) * 16,  v1, sB2[8 + j]);
        float ho = dotN_acc<16>(sW2 + (16 + j) * 16, v1, sB2[16 + j]);
        UNIT(hi, gg, ho, v2[j]);
    }
    float v3[16];
#pragma unroll
    for (int j = 0; j < 16; j++) {
        float hi = dotN_acc<8>(sW3 + j * 8,        v2, sB3[j]);
        float gg = dotN_acc<8>(sW3 + (16 + j) * 8, v2, sB3[16 + j]);
        float ho = dotN_acc<8>(sW3 + (32 + j) * 8, v2, sB3[32 + j]);
        UNIT(hi, gg, ho, v3[j]);
    }
    float r = sDob;
#pragma unroll
    for (int j = 0; j < 32; j++) {
        float hi = dotN_acc<16>(sW4 + j * 16,        v3, sB4[j]);
        float gg = dotN_acc<16>(sW4 + (32 + j) * 16, v3, sB4[32 + j]);
        float ho = dotN_acc<16>(sW4 + (64 + j) * 16, v3, sB4[64 + j]);
        float v4;
        UNIT(hi, gg, ho, v4);
        r = fmaf(v4, sDow[j], r);
    }
#undef UNIT

    out[(size_t)BS + idx] = r;
    out[3 * (size_t)BS + idx] = sRec[s];
}

// ---------------------------------------------------------------------------
extern "C" void kernel_launch(void* const* d_in, const int* in_sizes, int n_in,
                              void* d_out, int out_size)
{
    const float* values = (const float*)d_in[0];
    const int*   masks  = (const int*)  d_in[1];
    const float* gfW = (const float*)d_in[2];
    const float* gfU = (const float*)d_in[3];
    const float* gfb = (const float*)d_in[4];
    const float* gbW = (const float*)d_in[5];
    const float* gbU = (const float*)d_in[6];
    const float* gbb = (const float*)d_in[7];
    const float* impW = (const float*)d_in[8];
    const float* impB = (const float*)d_in[9];
    const float* fcW  = (const float*)d_in[10];
    const float* fcB  = (const float*)d_in[11];
    const float* dWih = (const float*)d_in[12];
    const float* dWhh = (const float*)d_in[13];
    const float* db_  = (const float*)d_in[14];
    const float* dOW  = (const float*)d_in[15];
    const float* dOB  = (const float*)d_in[16];
    const float* dow  = (const float*)d_in[17];
    const float* dob  = (const float*)d_in[18];
    const float* W0 = (const float*)d_in[19]; const float* b0 = (const float*)d_in[20];
    const float* W1 = (const float*)d_in[21]; const float* b1 = (const float*)d_in[22];
    const float* W2 = (const float*)d_in[23]; const float* b2 = (const float*)d_in[24];
    const float* W3 = (const float*)d_in[25]; const float* b3 = (const float*)d_in[26];
    const float* W4 = (const float*)d_in[27]; const float* b4 = (const float*)d_in[28];

    float* out = (float*)d_out;
    int B  = in_sizes[0] / 16;     // 32768
    int BS = B * 16;               // 524288
    int NB = (B + 127) / 128;      // 256

    gen_kernel<<<2 * NB + 1, 128>>>(values, masks, gfU, gfW, gfb, gbU, gbW, gbb,
                                    impW, impB, dWih, dWhh, db_, dOW, dOB, B);
    disc_kernel<<<(BS + 255) / 256, 256>>>(values, masks, fcW, fcB,
                                           W0, b0, W1, b1, W2, b2, W3, b3, W4, b4,
                                           dow, dob, out, BS);
}